// round 4
// baseline (speedup 1.0000x reference)
#include <cuda_runtime.h>

// ---------------- static device scratch (no allocation allowed) ----------------
#define MAXN 100000
__device__ float g_h0[MAXN * 64];     // agg (zeroed, scatter adds; GEMM1 adds x)
__device__ float g_h1[MAXN * 128];    // relu(h0 @ W1 + b1)  (BN1 folded into W2)
__device__ float g_W2f[128 * 128];    // BN1-folded W2
__device__ float g_b2f[128];          // BN1-folded b2
__device__ float g_sum1[128], g_ss1[128];
__device__ float g_sum2[128], g_ss2[128];
__device__ float g_a2[128], g_c2[128];
__device__ int   g_is64;

#define BN_EPS 1e-5f

// packed f32x2 FMA (sm_103a; PTX-only)
#define FMA2(d, a, b, c) \
    asm("fma.rn.f32x2 %0, %1, %2, %3;" : "=l"(d) : "l"(a), "l"(b), "l"(c))
#define DUP_F32X2(d, f) \
    asm("mov.b64 %0, {%1, %1};" : "=l"(d) : "f"(f))
#define UNPACK_F32X2(lo, hi, p) \
    asm("mov.b64 {%0, %1}, %2;" : "=f"(lo), "=f"(hi) : "l"(p))

// ---------------- zero per-launch stats ----------------
__global__ void k_zero_stats() {
    int j = threadIdx.x;
    if (j < 128) {
        g_sum1[j] = 0.f; g_ss1[j] = 0.f;
        g_sum2[j] = 0.f; g_ss2[j] = 0.f;
    }
}

// ---------------- zero g_h0 ----------------
__global__ void k_zero_h0(int n4) {
    float4* d = (float4*)g_h0;
    int stride = gridDim.x * blockDim.x;
    float4 z = make_float4(0.f, 0.f, 0.f, 0.f);
    for (int i = blockIdx.x * blockDim.x + threadIdx.x; i < n4; i += stride)
        d[i] = z;
}

// ---------------- detect int64 vs int32 edge_index ----------------
__global__ void k_detect(const int* __restrict__ idx, int n_pairs) {
    __shared__ int nz;
    if (threadIdx.x == 0) nz = 0;
    __syncthreads();
    int lim = n_pairs < 1024 ? n_pairs : 1024;
    for (int i = threadIdx.x; i < lim; i += blockDim.x)
        if (idx[2 * i + 1] != 0) nz = 1;   // benign race
    __syncthreads();
    if (threadIdx.x == 0) g_is64 = (nz == 0) ? 1 : 0;
}

// ---------------- edge scatter: h0[dst] += x[src]  (vector RED, L2-resident) ----------------
__global__ void k_scatter(const void* __restrict__ eptr, const float* __restrict__ x, int E) {
    const int is64 = g_is64;
    const long long total = (long long)E * 16;
    const long long stride = (long long)gridDim.x * blockDim.x;
    for (long long i = (long long)blockIdx.x * blockDim.x + threadIdx.x; i < total; i += stride) {
        int e = (int)(i >> 4);
        int c = (int)(i & 15);
        int src, dst;
        if (is64) {
            const long long* p = (const long long*)eptr;
            src = (int)p[e];
            dst = (int)p[E + e];
        } else {
            const int* p = (const int*)eptr;
            src = p[e];
            dst = p[E + e];
        }
        float4 v = __ldg((const float4*)x + (long long)src * 16 + c);
        float* d = g_h0 + (long long)dst * 64 + c * 4;
        asm volatile("red.global.add.v4.f32 [%0], {%1,%2,%3,%4};"
                     :: "l"(d), "f"(v.x), "f"(v.y), "f"(v.z), "f"(v.w) : "memory");
    }
}

// ---------------- persistent double-buffered GEMM + relu + fused BN stats ----------------
// 148 blocks x 512 threads. W (K x 128) staged to smem ONCE. X tiles (128 x K)
// double-buffered; next tile's LDGs issued before computing current tile.
// Warp w -> rows w*8..w*8+7 of tile; lane j -> cols j*4..j*4+3.
// Per k per lane: 1 conflict-free LDS.128 of W + broadcast x + 2 FFMA2.
// BN stats accumulate in registers across all tiles; one atomic flush at end.
template <int K, bool ADDX>
__global__ void __launch_bounds__(512, 1)
k_gemm_relu_stats(const float* __restrict__ X, const float* __restrict__ X2,
                  const float* __restrict__ W, const float* __restrict__ B,
                  float* __restrict__ Y, int N, int ntiles,
                  float* __restrict__ gsum, float* __restrict__ gss) {
    extern __shared__ float smem[];
    float* sw  = smem;                 // K * 128
    float* sx0 = smem + K * 128;       // 128 * K
    float* sx1 = sx0 + 128 * K;        // 128 * K

    const int tid  = threadIdx.x;
    const int w    = tid >> 5;
    const int lane = tid & 31;
    constexpr int NF4  = 128 * (K / 4);   // float4s per X tile
    constexpr int PREF = NF4 / 512;       // float4s per thread (8 @K=128, 4 @K=64)

    // stage W once (K*128 floats = K*32 float4, contiguous)
    for (int f = tid; f < K * 32; f += 512)
        ((float4*)sw)[f] = __ldg((const float4*)W + f);

    // prefetch helper: tile -> regs
    float4 pf[PREF];
    int tile = blockIdx.x;

    auto prefetch = [&](int t) {
#pragma unroll
        for (int i = 0; i < PREF; i++) {
            int f   = tid + i * 512;
            int r   = f / (K / 4);
            int c4  = f % (K / 4);
            int row = t * 128 + r;
            float4 v = make_float4(0.f, 0.f, 0.f, 0.f);
            if (row < N) {
                v = __ldg((const float4*)(X + (long long)row * K) + c4);
                if (ADDX) {
                    float4 u = __ldg((const float4*)(X2 + (long long)row * K) + c4);
                    v.x += u.x; v.y += u.y; v.z += u.z; v.w += u.w;
                }
            }
            pf[i] = v;
        }
    };
    auto store_tile = [&](float* sx) {
#pragma unroll
        for (int i = 0; i < PREF; i++) {
            int f  = tid + i * 512;
            int r  = f / (K / 4);
            int c4 = f % (K / 4);
            ((float4*)(sx + r * K))[c4] = pf[i];
        }
    };

    if (tile < ntiles) prefetch(tile);
    store_tile(sx0);
    __syncthreads();

    // per-thread bias (4 cols) + running stats
    float4 bias = __ldg((const float4*)B + lane);
    float csum[4] = {0.f, 0.f, 0.f, 0.f};
    float csq[4]  = {0.f, 0.f, 0.f, 0.f};

    int p = 0;
    for (; tile < ntiles; tile += gridDim.x) {
        int tnext = tile + gridDim.x;
        if (tnext < ntiles) prefetch(tnext);   // LDGs in flight during compute

        const float* sx = p ? sx1 : sx0;
        const float* xb = sx + (w * 8) * K;
        const float* wl = sw + lane * 4;

        unsigned long long acc[8][2];
#pragma unroll
        for (int i = 0; i < 8; i++) { acc[i][0] = 0ULL; acc[i][1] = 0ULL; }

        for (int k0 = 0; k0 < K; k0 += 4) {
            float4 xv[8];
#pragma unroll
            for (int i = 0; i < 8; i++)
                xv[i] = *(const float4*)(xb + i * K + k0);
#pragma unroll
            for (int kk = 0; kk < 4; kk++) {
                ulonglong2 wv = *(const ulonglong2*)(wl + (k0 + kk) * 128);
#pragma unroll
                for (int i = 0; i < 8; i++) {
                    float xs = (kk == 0) ? xv[i].x : (kk == 1) ? xv[i].y
                             : (kk == 2) ? xv[i].z : xv[i].w;
                    unsigned long long xp;
                    DUP_F32X2(xp, xs);
                    FMA2(acc[i][0], xp, wv.x, acc[i][0]);
                    FMA2(acc[i][1], xp, wv.y, acc[i][1]);
                }
            }
        }

        // epilogue: bias + relu + stats + store
        int row0 = tile * 128 + w * 8;
#pragma unroll
        for (int i = 0; i < 8; i++) {
            int row = row0 + i;
            if (row < N) {
                float o[4];
                UNPACK_F32X2(o[0], o[1], acc[i][0]);
                UNPACK_F32X2(o[2], o[3], acc[i][1]);
                o[0] = fmaxf(o[0] + bias.x, 0.f);
                o[1] = fmaxf(o[1] + bias.y, 0.f);
                o[2] = fmaxf(o[2] + bias.z, 0.f);
                o[3] = fmaxf(o[3] + bias.w, 0.f);
#pragma unroll
                for (int j = 0; j < 4; j++) {
                    csum[j] += o[j];
                    csq[j]  = fmaf(o[j], o[j], csq[j]);
                }
                ((float4*)(Y + (long long)row * 128))[lane] =
                    make_float4(o[0], o[1], o[2], o[3]);
            }
        }

        __syncthreads();                 // everyone done reading sx[p]
        if (tnext < ntiles) {
            store_tile(p ? sx0 : sx1);   // fill the other buffer
            p ^= 1;
        }
        __syncthreads();
    }

    // flush stats: 128 target addresses, 16-warp redundancy -> 4096 REDs
#pragma unroll
    for (int j = 0; j < 4; j++) {
        atomicAdd(&gsum[lane * 4 + j], csum[j]);
        atomicAdd(&gss[lane * 4 + j], csq[j]);
    }
}

// ---------------- fold BN1 into W2/b2 ----------------
__global__ void k_fold1(const float* __restrict__ W2, const float* __restrict__ b2,
                        const float* __restrict__ g1, const float* __restrict__ be1,
                        float invN) {
    __shared__ float a_s[128], c_s[128];
    int j = threadIdx.x;
    float mean = g_sum1[j] * invN;
    float var  = g_ss1[j] * invN - mean * mean;
    float a    = g1[j] * rsqrtf(var + BN_EPS);
    a_s[j] = a;
    c_s[j] = be1[j] - a * mean;
    __syncthreads();
    float acc = 0.f;
    for (int k = 0; k < 128; k++) {
        float w = W2[k * 128 + j];
        g_W2f[k * 128 + j] = a_s[k] * w;
        acc = fmaf(c_s[k], w, acc);
    }
    g_b2f[j] = b2[j] + acc;
}

// ---------------- BN2 coefficients ----------------
__global__ void k_a2c2(const float* __restrict__ g2, const float* __restrict__ be2, float invN) {
    int j = threadIdx.x;
    float mean = g_sum2[j] * invN;
    float var  = g_ss2[j] * invN - mean * mean;
    float a    = g2[j] * rsqrtf(var + BN_EPS);
    g_a2[j] = a;
    g_c2[j] = be2[j] - a * mean;
}

// ---------------- BN2 apply in place on d_out ----------------
__global__ void k_bn2(float4* __restrict__ Y, int n4) {
    int stride = gridDim.x * blockDim.x;
    for (int i = blockIdx.x * blockDim.x + threadIdx.x; i < n4; i += stride) {
        int c4 = i & 31;
        float4 v = Y[i];
        float4 a = __ldg((const float4*)g_a2 + c4);
        float4 c = __ldg((const float4*)g_c2 + c4);
        v.x = fmaf(a.x, v.x, c.x);
        v.y = fmaf(a.y, v.y, c.y);
        v.z = fmaf(a.z, v.z, c.z);
        v.w = fmaf(a.w, v.w, c.w);
        Y[i] = v;
    }
}

// ---------------- launcher ----------------
extern "C" void kernel_launch(void* const* d_in, const int* in_sizes, int n_in,
                              void* d_out, int out_size) {
    const float* x   = (const float*)d_in[0];
    const void*  eix = d_in[1];
    const float* W1  = (const float*)d_in[2];
    const float* b1  = (const float*)d_in[3];
    const float* g1  = (const float*)d_in[4];
    const float* be1 = (const float*)d_in[5];
    const float* W2  = (const float*)d_in[6];
    const float* b2  = (const float*)d_in[7];
    const float* g2  = (const float*)d_in[8];
    const float* be2 = (const float*)d_in[9];
    float* out = (float*)d_out;

    const int N = in_sizes[0] / 64;
    const int E = in_sizes[1] / 2;

    const int SMEM1 = (64 * 128 + 2 * 128 * 64) * 4;    //  96 KB
    const int SMEM2 = (128 * 128 + 2 * 128 * 128) * 4;  // 192 KB
    cudaFuncSetAttribute(k_gemm_relu_stats<64, true>,
                         cudaFuncAttributeMaxDynamicSharedMemorySize, SMEM1);
    cudaFuncSetAttribute(k_gemm_relu_stats<128, false>,
                         cudaFuncAttributeMaxDynamicSharedMemorySize, SMEM2);

    void *p_h0, *p_h1, *p_W2f, *p_b2f, *p_s1, *p_q1, *p_s2, *p_q2;
    cudaGetSymbolAddress(&p_h0, g_h0);
    cudaGetSymbolAddress(&p_h1, g_h1);
    cudaGetSymbolAddress(&p_W2f, g_W2f);
    cudaGetSymbolAddress(&p_b2f, g_b2f);
    cudaGetSymbolAddress(&p_s1, g_sum1);
    cudaGetSymbolAddress(&p_q1, g_ss1);
    cudaGetSymbolAddress(&p_s2, g_sum2);
    cudaGetSymbolAddress(&p_q2, g_ss2);

    const int GB = 148 * 8;
    const int ntiles = (N + 127) / 128;
    const int gb = ntiles < 148 ? ntiles : 148;
    const float invN = 1.0f / (float)N;

    k_zero_stats<<<1, 128>>>();
    k_detect<<<1, 256>>>((const int*)eix, E);
    k_zero_h0<<<GB, 256>>>(N * 16);
    k_scatter<<<GB * 2, 256>>>(eix, x, E);
    k_gemm_relu_stats<64, true><<<gb, 512, SMEM1>>>(
        (const float*)p_h0, x, W1, b1, (float*)p_h1, N, ntiles,
        (float*)p_s1, (float*)p_q1);
    k_fold1<<<1, 128>>>(W2, b2, g1, be1, invN);
    k_gemm_relu_stats<128, false><<<gb, 512, SMEM2>>>(
        (const float*)p_h1, nullptr, (const float*)p_W2f, (const float*)p_b2f, out, N,
        ntiles, (float*)p_s2, (float*)p_q2);
    k_a2c2<<<1, 128>>>(g2, be2, invN);
    k_bn2<<<GB, 256>>>((float4*)out, N * 32);
}

// round 5
// speedup vs baseline: 1.0104x; 1.0104x over previous
#include <cuda_runtime.h>

// ---------------- static device scratch (no allocation allowed) ----------------
#define MAXN 100000
__device__ float g_h0[MAXN * 64];     // x + agg
__device__ float g_h1[MAXN * 128];    // relu(h0 @ W1 + b1)  (BN1 folded into W2)
__device__ float g_W2f[128 * 128];    // BN1-folded W2
__device__ float g_b2f[128];          // BN1-folded b2
__device__ float g_sum1[128], g_ss1[128];
__device__ float g_sum2[128], g_ss2[128];
__device__ float g_a2[128], g_c2[128];
__device__ int   g_is64;

#define BN_EPS 1e-5f

// packed f32x2 FMA (sm_103a; PTX-only)
#define FMA2(d, a, b, c) \
    asm("fma.rn.f32x2 %0, %1, %2, %3;" : "=l"(d) : "l"(a), "l"(b), "l"(c))
#define DUP_F32X2(d, f) \
    asm("mov.b64 %0, {%1, %1};" : "=l"(d) : "f"(f))
#define UNPACK_F32X2(lo, hi, p) \
    asm("mov.b64 {%0, %1}, %2;" : "=f"(lo), "=f"(hi) : "l"(p))

// ---------------- zero per-launch stats ----------------
__global__ void k_zero_stats() {
    int j = threadIdx.x;
    if (j < 128) {
        g_sum1[j] = 0.f; g_ss1[j] = 0.f;
        g_sum2[j] = 0.f; g_ss2[j] = 0.f;
    }
}

// ---------------- detect int64 vs int32 edge_index ----------------
__global__ void k_detect(const int* __restrict__ idx, int n_pairs) {
    __shared__ int nz;
    if (threadIdx.x == 0) nz = 0;
    __syncthreads();
    int lim = n_pairs < 1024 ? n_pairs : 1024;
    for (int i = threadIdx.x; i < lim; i += blockDim.x)
        if (idx[2 * i + 1] != 0) nz = 1;   // benign race
    __syncthreads();
    if (threadIdx.x == 0) g_is64 = (nz == 0) ? 1 : 0;
}

// ---------------- h0 = x (copy; scatter REDs on top) ----------------
__global__ void k_copy(const float4* __restrict__ x, int n4) {
    float4* d = (float4*)g_h0;
    int stride = gridDim.x * blockDim.x;
    for (int i = blockIdx.x * blockDim.x + threadIdx.x; i < n4; i += stride)
        d[i] = x[i];
}

// ---------------- edge scatter: h0[dst] += x[src]  (vector RED, L2-resident) ----------------
__global__ void k_scatter(const void* __restrict__ eptr, const float* __restrict__ x, int E) {
    const int is64 = g_is64;
    const long long total = (long long)E * 16;
    const long long stride = (long long)gridDim.x * blockDim.x;
    for (long long i = (long long)blockIdx.x * blockDim.x + threadIdx.x; i < total; i += stride) {
        int e = (int)(i >> 4);
        int c = (int)(i & 15);
        int src, dst;
        if (is64) {
            const long long* p = (const long long*)eptr;
            src = (int)p[e];
            dst = (int)p[E + e];
        } else {
            const int* p = (const int*)eptr;
            src = p[e];
            dst = p[E + e];
        }
        float4 v = __ldg((const float4*)x + (long long)src * 16 + c);
        float* d = g_h0 + (long long)dst * 64 + c * 4;
        asm volatile("red.global.add.v4.f32 [%0], {%1,%2,%3,%4};"
                     :: "l"(d), "f"(v.x), "f"(v.y), "f"(v.z), "f"(v.w) : "memory");
    }
}

// ---------------- persistent GEMM, cp.async double-buffered, FFMA2, fused BN stats ----
// 148 blocks x 512 threads. W staged once. X tiles (128 x K) staged with
// cp.async.cg (no register cost), one commit-group per tile, wait_group 1.
// Warp w -> rows w*8..+7; lane -> cols lane*4..+3.
template <int K>
__global__ void __launch_bounds__(512, 1)
k_gemm_relu_stats(const float* __restrict__ X, const float* __restrict__ W,
                  const float* __restrict__ B, float* __restrict__ Y,
                  int N, int ntiles,
                  float* __restrict__ gsum, float* __restrict__ gss) {
    extern __shared__ float smem[];
    float* sw  = smem;                 // K * 128
    float* sx0 = smem + K * 128;       // 128 * K
    float* sx1 = sx0 + 128 * K;        // 128 * K

    const int tid  = threadIdx.x;
    const int w    = tid >> 5;
    const int lane = tid & 31;
    constexpr int NF4 = 128 * (K / 4);
    constexpr int CPT = NF4 / 512;     // cp.asyncs per thread per tile

    // stage W once
    for (int f = tid; f < K * 32; f += 512)
        ((float4*)sw)[f] = __ldg((const float4*)W + f);

    auto issue_tile = [&](int t, float* sx) {
#pragma unroll
        for (int i = 0; i < CPT; i++) {
            int f  = tid + i * 512;
            int r  = f / (K / 4);
            int c4 = f % (K / 4);
            int row = t * 128 + r;
            int rc  = row < N ? row : (N - 1);          // clamp (bytes=0 masks)
            const float4* g = (const float4*)(X + (long long)rc * K) + c4;
            unsigned sa = (unsigned)__cvta_generic_to_shared((float4*)(sx + r * K) + c4);
            int bytes = (row < N) ? 16 : 0;
            asm volatile("cp.async.cg.shared.global [%0], [%1], 16, %2;"
                         :: "r"(sa), "l"(g), "r"(bytes));
        }
        asm volatile("cp.async.commit_group;");
    };

    int tile = blockIdx.x;
    if (tile < ntiles) issue_tile(tile, sx0);

    float4 bias = __ldg((const float4*)B + lane);
    float csum[4] = {0.f, 0.f, 0.f, 0.f};
    float csq[4]  = {0.f, 0.f, 0.f, 0.f};

    int p = 0;
    for (; tile < ntiles; tile += gridDim.x) {
        int tnext = tile + gridDim.x;
        if (tnext < ntiles) {
            issue_tile(tnext, p ? sx0 : sx1);
            asm volatile("cp.async.wait_group 1;");
        } else {
            asm volatile("cp.async.wait_group 0;");
        }
        __syncthreads();

        const float* sx = p ? sx1 : sx0;
        const float* xb = sx + (w * 8) * K;
        const float* wl = sw + lane * 4;

        unsigned long long acc[8][2];
#pragma unroll
        for (int i = 0; i < 8; i++) { acc[i][0] = 0ULL; acc[i][1] = 0ULL; }

        for (int k0 = 0; k0 < K; k0 += 4) {
            float4 xv[8];
#pragma unroll
            for (int i = 0; i < 8; i++)
                xv[i] = *(const float4*)(xb + i * K + k0);
#pragma unroll
            for (int kk = 0; kk < 4; kk++) {
                ulonglong2 wv = *(const ulonglong2*)(wl + (k0 + kk) * 128);
#pragma unroll
                for (int i = 0; i < 8; i++) {
                    float xs = (kk == 0) ? xv[i].x : (kk == 1) ? xv[i].y
                             : (kk == 2) ? xv[i].z : xv[i].w;
                    unsigned long long xp;
                    DUP_F32X2(xp, xs);
                    FMA2(acc[i][0], xp, wv.x, acc[i][0]);
                    FMA2(acc[i][1], xp, wv.y, acc[i][1]);
                }
            }
        }

        // epilogue: bias + relu + stats + store
        int row0 = tile * 128 + w * 8;
#pragma unroll
        for (int i = 0; i < 8; i++) {
            int row = row0 + i;
            if (row < N) {
                float o[4];
                UNPACK_F32X2(o[0], o[1], acc[i][0]);
                UNPACK_F32X2(o[2], o[3], acc[i][1]);
                o[0] = fmaxf(o[0] + bias.x, 0.f);
                o[1] = fmaxf(o[1] + bias.y, 0.f);
                o[2] = fmaxf(o[2] + bias.z, 0.f);
                o[3] = fmaxf(o[3] + bias.w, 0.f);
#pragma unroll
                for (int j = 0; j < 4; j++) {
                    csum[j] += o[j];
                    csq[j]  = fmaf(o[j], o[j], csq[j]);
                }
                ((float4*)(Y + (long long)row * 128))[lane] =
                    make_float4(o[0], o[1], o[2], o[3]);
            }
        }

        __syncthreads();   // done reading sx[p]; next iter issues into it
        p ^= 1;
    }

    // flush stats
#pragma unroll
    for (int j = 0; j < 4; j++) {
        atomicAdd(&gsum[lane * 4 + j], csum[j]);
        atomicAdd(&gss[lane * 4 + j], csq[j]);
    }
}

// ---------------- fold BN1 into W2/b2 ----------------
__global__ void k_fold1(const float* __restrict__ W2, const float* __restrict__ b2,
                        const float* __restrict__ g1, const float* __restrict__ be1,
                        float invN) {
    __shared__ float a_s[128], c_s[128];
    int j = threadIdx.x;
    float mean = g_sum1[j] * invN;
    float var  = g_ss1[j] * invN - mean * mean;
    float a    = g1[j] * rsqrtf(var + BN_EPS);
    a_s[j] = a;
    c_s[j] = be1[j] - a * mean;
    __syncthreads();
    float acc = 0.f;
    for (int k = 0; k < 128; k++) {
        float w = W2[k * 128 + j];
        g_W2f[k * 128 + j] = a_s[k] * w;
        acc = fmaf(c_s[k], w, acc);
    }
    g_b2f[j] = b2[j] + acc;
}

// ---------------- BN2 coefficients ----------------
__global__ void k_a2c2(const float* __restrict__ g2, const float* __restrict__ be2, float invN) {
    int j = threadIdx.x;
    float mean = g_sum2[j] * invN;
    float var  = g_ss2[j] * invN - mean * mean;
    float a    = g2[j] * rsqrtf(var + BN_EPS);
    g_a2[j] = a;
    g_c2[j] = be2[j] - a * mean;
}

// ---------------- BN2 apply in place on d_out ----------------
__global__ void k_bn2(float4* __restrict__ Y, int n4) {
    int stride = gridDim.x * blockDim.x;
    for (int i = blockIdx.x * blockDim.x + threadIdx.x; i < n4; i += stride) {
        int c4 = i & 31;
        float4 v = Y[i];
        float4 a = __ldg((const float4*)g_a2 + c4);
        float4 c = __ldg((const float4*)g_c2 + c4);
        v.x = fmaf(a.x, v.x, c.x);
        v.y = fmaf(a.y, v.y, c.y);
        v.z = fmaf(a.z, v.z, c.z);
        v.w = fmaf(a.w, v.w, c.w);
        Y[i] = v;
    }
}

// ---------------- launcher ----------------
extern "C" void kernel_launch(void* const* d_in, const int* in_sizes, int n_in,
                              void* d_out, int out_size) {
    const float* x   = (const float*)d_in[0];
    const void*  eix = d_in[1];
    const float* W1  = (const float*)d_in[2];
    const float* b1  = (const float*)d_in[3];
    const float* g1  = (const float*)d_in[4];
    const float* be1 = (const float*)d_in[5];
    const float* W2  = (const float*)d_in[6];
    const float* b2  = (const float*)d_in[7];
    const float* g2  = (const float*)d_in[8];
    const float* be2 = (const float*)d_in[9];
    float* out = (float*)d_out;

    const int N = in_sizes[0] / 64;
    const int E = in_sizes[1] / 2;

    const int SMEM1 = (64 * 128 + 2 * 128 * 64) * 4;    //  96 KB
    const int SMEM2 = (128 * 128 + 2 * 128 * 128) * 4;  // 192 KB
    cudaFuncSetAttribute(k_gemm_relu_stats<64>,
                         cudaFuncAttributeMaxDynamicSharedMemorySize, SMEM1);
    cudaFuncSetAttribute(k_gemm_relu_stats<128>,
                         cudaFuncAttributeMaxDynamicSharedMemorySize, SMEM2);

    void *p_h0, *p_h1, *p_W2f, *p_b2f, *p_s1, *p_q1, *p_s2, *p_q2;
    cudaGetSymbolAddress(&p_h0, g_h0);
    cudaGetSymbolAddress(&p_h1, g_h1);
    cudaGetSymbolAddress(&p_W2f, g_W2f);
    cudaGetSymbolAddress(&p_b2f, g_b2f);
    cudaGetSymbolAddress(&p_s1, g_sum1);
    cudaGetSymbolAddress(&p_q1, g_ss1);
    cudaGetSymbolAddress(&p_s2, g_sum2);
    cudaGetSymbolAddress(&p_q2, g_ss2);

    const int GB = 148 * 8;
    const int ntiles = (N + 127) / 128;
    const int gb = ntiles < 148 ? ntiles : 148;
    const float invN = 1.0f / (float)N;

    k_zero_stats<<<1, 128>>>();
    k_detect<<<1, 256>>>((const int*)eix, E);
    k_copy<<<GB, 256>>>((const float4*)x, N * 16);
    k_scatter<<<GB * 2, 256>>>(eix, x, E);
    k_gemm_relu_stats<64><<<gb, 512, SMEM1>>>(
        (const float*)p_h0, W1, b1, (float*)p_h1, N, ntiles,
        (float*)p_s1, (float*)p_q1);
    k_fold1<<<1, 128>>>(W2, b2, g1, be1, invN);
    k_gemm_relu_stats<128><<<gb, 512, SMEM2>>>(
        (const float*)p_h1, (const float*)p_W2f, (const float*)p_b2f, out, N,
        ntiles, (float*)p_s2, (float*)p_q2);
    k_a2c2<<<1, 128>>>(g2, be2, invN);
    k_bn2<<<GB, 256>>>((float4*)out, N * 32);
}

// round 7
// speedup vs baseline: 1.6362x; 1.6193x over previous
#include <cuda_runtime.h>
#include <cuda_bf16.h>
#include <cstdint>

// ---------------- static device scratch (no allocation allowed) ----------------
#define MAXN 100000
__device__ float g_h0[MAXN * 64];     // x + agg
__device__ float g_h1[MAXN * 128];    // relu(h0 @ W1 + b1)
__device__ float g_W2f[128 * 128];    // BN1-folded W2
__device__ float g_b2f[128];          // BN1-folded b2
__device__ float g_sum1[128], g_ss1[128];
__device__ float g_sum2[128], g_ss2[128];
__device__ float g_a2[128], g_c2[128];
__device__ int   g_is64;

#define BN_EPS 1e-5f

// ---------------- warp-MMA helpers (base ISA, sm_80+: legal on compute_103) ----
#define LDSM4(r, a)                                                            \
    asm volatile("ldmatrix.sync.aligned.m8n8.x4.shared.b16 {%0,%1,%2,%3}, [%4];" \
                 : "=r"((r)[0]), "=r"((r)[1]), "=r"((r)[2]), "=r"((r)[3])      \
                 : "r"(a))
#define LDSM4T(r, a)                                                           \
    asm volatile("ldmatrix.sync.aligned.m8n8.x4.trans.shared.b16 {%0,%1,%2,%3}, [%4];" \
                 : "=r"((r)[0]), "=r"((r)[1]), "=r"((r)[2]), "=r"((r)[3])      \
                 : "r"(a))
#define MMA16816(d, a, b0, b1)                                                 \
    asm volatile("mma.sync.aligned.m16n8k16.row.col.f32.bf16.bf16.f32 "        \
                 "{%0,%1,%2,%3}, {%4,%5,%6,%7}, {%8,%9}, {%0,%1,%2,%3};"       \
                 : "+f"((d)[0]), "+f"((d)[1]), "+f"((d)[2]), "+f"((d)[3])      \
                 : "r"((a)[0]), "r"((a)[1]), "r"((a)[2]), "r"((a)[3]),         \
                   "r"(b0), "r"(b1))

__device__ __forceinline__ uint32_t smem_u32(const void* p) {
    return (uint32_t)__cvta_generic_to_shared(p);
}
// fp32 pair -> bf16x2 hi word + bf16x2 lo (residual) word
__device__ __forceinline__ void pack_pair(float vx, float vy, unsigned& hi, unsigned& lo) {
    __nv_bfloat16 h0 = __float2bfloat16(vx);
    __nv_bfloat16 h1 = __float2bfloat16(vy);
    __nv_bfloat16 l0 = __float2bfloat16(vx - __bfloat162float(h0));
    __nv_bfloat16 l1 = __float2bfloat16(vy - __bfloat162float(h1));
    hi = ((unsigned)__bfloat16_as_ushort(h1) << 16) | __bfloat16_as_ushort(h0);
    lo = ((unsigned)__bfloat16_as_ushort(l1) << 16) | __bfloat16_as_ushort(l0);
}

// ---------------- small pipeline kernels (unchanged) ----------------
__global__ void k_zero_stats() {
    int j = threadIdx.x;
    if (j < 128) { g_sum1[j] = 0.f; g_ss1[j] = 0.f; g_sum2[j] = 0.f; g_ss2[j] = 0.f; }
}
__global__ void k_detect(const int* __restrict__ idx, int n_pairs) {
    __shared__ int nz;
    if (threadIdx.x == 0) nz = 0;
    __syncthreads();
    int lim = n_pairs < 1024 ? n_pairs : 1024;
    for (int i = threadIdx.x; i < lim; i += blockDim.x)
        if (idx[2 * i + 1] != 0) nz = 1;
    __syncthreads();
    if (threadIdx.x == 0) g_is64 = (nz == 0) ? 1 : 0;
}
__global__ void k_copy(const float4* __restrict__ x, int n4) {
    float4* d = (float4*)g_h0;
    int stride = gridDim.x * blockDim.x;
    for (int i = blockIdx.x * blockDim.x + threadIdx.x; i < n4; i += stride)
        d[i] = x[i];
}
__global__ void k_scatter(const void* __restrict__ eptr, const float* __restrict__ x, int E) {
    const int is64 = g_is64;
    const long long total = (long long)E * 16;
    const long long stride = (long long)gridDim.x * blockDim.x;
    for (long long i = (long long)blockIdx.x * blockDim.x + threadIdx.x; i < total; i += stride) {
        int e = (int)(i >> 4);
        int c = (int)(i & 15);
        int src, dst;
        if (is64) {
            const long long* p = (const long long*)eptr;
            src = (int)p[e]; dst = (int)p[E + e];
        } else {
            const int* p = (const int*)eptr;
            src = p[e]; dst = p[E + e];
        }
        float4 v = __ldg((const float4*)x + (long long)src * 16 + c);
        float* d = g_h0 + (long long)dst * 64 + c * 4;
        asm volatile("red.global.add.v4.f32 [%0], {%1,%2,%3,%4};"
                     :: "l"(d), "f"(v.x), "f"(v.y), "f"(v.z), "f"(v.w) : "memory");
    }
}

// ---------------- persistent bf16-split tensor-core GEMM + relu + BN stats -----
// Y[N,128] = relu(X[N,K] @ W[K,128] + B), D = Ahi*Bhi + Ahi*Blo + Alo*Bhi.
// 512 thr = 16 warps in 4x4 grid; warp tile 32x32; mma.m16n8k16 bf16.
// A planes: row-major 128 x (K+8); W planes: native (k,n) 128-col +8 pad,
// read with ldmatrix.x4.trans. W staged once; X tile per iteration.
template <int K>
__global__ void __launch_bounds__(512, 1)
k_gemm_mma(const float* __restrict__ X, const float* __restrict__ W,
           const float* __restrict__ B, float* __restrict__ Y,
           int N, int ntiles, float* __restrict__ gsum, float* __restrict__ gss) {
    constexpr int AS = K + 8;        // A row stride (bf16 units)
    constexpr int WS = 128 + 8;      // W row stride (bf16 units)
    extern __shared__ __nv_bfloat16 sm[];
    __nv_bfloat16* a_hi = sm;                    // 128*AS
    __nv_bfloat16* a_lo = a_hi + 128 * AS;       // 128*AS
    __nv_bfloat16* w_hi = a_lo + 128 * AS;       // K*WS
    __nv_bfloat16* w_lo = w_hi + K * WS;         // K*WS

    const int tid    = threadIdx.x;
    const int wid    = tid >> 5;
    const int lane   = tid & 31;
    const int warp_m = wid & 3;      // rows warp_m*32 ..
    const int warp_n = wid >> 2;     // cols warp_n*32 ..

    // ---- stage W hi/lo once (pairs along n) ----
    for (int f = tid; f < K * 64; f += 512) {
        int k  = f >> 6;
        int n2 = f & 63;
        float2 wv = *(const float2*)(W + (long long)k * 128 + n2 * 2);
        unsigned hi, lo;
        pack_pair(wv.x, wv.y, hi, lo);
        *(unsigned*)(w_hi + k * WS + n2 * 2) = hi;
        *(unsigned*)(w_lo + k * WS + n2 * 2) = lo;
    }

    // ---- per-thread constants ----
    const int rbase = lane >> 2;          // 0..7
    const int cquad = (lane & 3) * 2;     // 0,2,4,6
    // ldmatrix lane address bases
    const uint32_t aoff = ((warp_m * 32 + (lane & 15)) * AS + (lane >> 4) * 8) * 2;
    const uint32_t a_hi_base = smem_u32(a_hi) + aoff;
    const uint32_t a_lo_base = smem_u32(a_lo) + aoff;
    const uint32_t woff = ((lane & 15) * WS + warp_n * 32 + (lane >> 4) * 8) * 2;
    const uint32_t w_hi_base = smem_u32(w_hi) + woff;
    const uint32_t w_lo_base = smem_u32(w_lo) + woff;

    // bias + stats for my 8 columns (fixed across tiles)
    float bias2[4][2];
#pragma unroll
    for (int ni = 0; ni < 4; ni++) {
        bias2[ni][0] = __ldg(B + warp_n * 32 + ni * 8 + cquad);
        bias2[ni][1] = __ldg(B + warp_n * 32 + ni * 8 + cquad + 1);
    }
    float csum[8], csq[8];
#pragma unroll
    for (int j = 0; j < 8; j++) { csum[j] = 0.f; csq[j] = 0.f; }

    for (int tile = blockIdx.x; tile < ntiles; tile += gridDim.x) {
        const int row0 = tile * 128;
        __syncthreads();   // previous iter's ldmatrix reads done before overwrite

        // ---- stage X tile hi/lo (pairs along k), zero-pad OOB rows ----
        for (int f = tid; f < 128 * (K / 2); f += 512) {
            int r  = f / (K / 2);
            int c2 = f % (K / 2);
            float2 v = make_float2(0.f, 0.f);
            if (row0 + r < N)
                v = *(const float2*)(X + (long long)(row0 + r) * K + c2 * 2);
            unsigned hi, lo;
            pack_pair(v.x, v.y, hi, lo);
            *(unsigned*)(a_hi + r * AS + c2 * 2) = hi;
            *(unsigned*)(a_lo + r * AS + c2 * 2) = lo;
        }
        __syncthreads();

        // ---- compute ----
        float acc[2][4][4];
#pragma unroll
        for (int mi = 0; mi < 2; mi++)
#pragma unroll
            for (int ni = 0; ni < 4; ni++)
#pragma unroll
                for (int q = 0; q < 4; q++) acc[mi][ni][q] = 0.f;

#pragma unroll
        for (int k0 = 0; k0 < K; k0 += 16) {
            uint32_t ah[2][4], al[2][4];
            LDSM4(ah[0], a_hi_base + (0 * 16 * AS + k0) * 2);
            LDSM4(ah[1], a_hi_base + (1 * 16 * AS + k0) * 2);
            LDSM4(al[0], a_lo_base + (0 * 16 * AS + k0) * 2);
            LDSM4(al[1], a_lo_base + (1 * 16 * AS + k0) * 2);
            uint32_t bh0[4], bh1[4], bl0[4], bl1[4];
            LDSM4T(bh0, w_hi_base + (k0 * WS + 0) * 2);
            LDSM4T(bh1, w_hi_base + (k0 * WS + 16) * 2);
            LDSM4T(bl0, w_lo_base + (k0 * WS + 0) * 2);
            LDSM4T(bl1, w_lo_base + (k0 * WS + 16) * 2);
#pragma unroll
            for (int mi = 0; mi < 2; mi++) {
                // hi * hi
                MMA16816(acc[mi][0], ah[mi], bh0[0], bh0[1]);
                MMA16816(acc[mi][1], ah[mi], bh0[2], bh0[3]);
                MMA16816(acc[mi][2], ah[mi], bh1[0], bh1[1]);
                MMA16816(acc[mi][3], ah[mi], bh1[2], bh1[3]);
                // hi * lo
                MMA16816(acc[mi][0], ah[mi], bl0[0], bl0[1]);
                MMA16816(acc[mi][1], ah[mi], bl0[2], bl0[3]);
                MMA16816(acc[mi][2], ah[mi], bl1[0], bl1[1]);
                MMA16816(acc[mi][3], ah[mi], bl1[2], bl1[3]);
                // lo * hi
                MMA16816(acc[mi][0], al[mi], bh0[0], bh0[1]);
                MMA16816(acc[mi][1], al[mi], bh0[2], bh0[3]);
                MMA16816(acc[mi][2], al[mi], bh1[0], bh1[1]);
                MMA16816(acc[mi][3], al[mi], bh1[2], bh1[3]);
            }
        }

        // ---- epilogue: bias + relu + stats + store ----
#pragma unroll
        for (int mi = 0; mi < 2; mi++) {
#pragma unroll
            for (int ri = 0; ri < 2; ri++) {
                int row = row0 + warp_m * 32 + mi * 16 + ri * 8 + rbase;
                if (row < N) {
                    float* yr = Y + (long long)row * 128 + warp_n * 32;
#pragma unroll
                    for (int ni = 0; ni < 4; ni++) {
                        float o0 = fmaxf(acc[mi][ni][ri * 2 + 0] + bias2[ni][0], 0.f);
                        float o1 = fmaxf(acc[mi][ni][ri * 2 + 1] + bias2[ni][1], 0.f);
                        csum[ni * 2 + 0] += o0;
                        csum[ni * 2 + 1] += o1;
                        csq[ni * 2 + 0] = fmaf(o0, o0, csq[ni * 2 + 0]);
                        csq[ni * 2 + 1] = fmaf(o1, o1, csq[ni * 2 + 1]);
                        *(float2*)(yr + ni * 8 + cquad) = make_float2(o0, o1);
                    }
                }
            }
        }
    }

    // ---- flush BN stats: reduce over the 8 lanes sharing each column ----
#pragma unroll
    for (int j = 0; j < 8; j++) {
        float s = csum[j], q = csq[j];
#pragma unroll
        for (int o = 4; o <= 16; o <<= 1) {
            s += __shfl_xor_sync(0xFFFFFFFFu, s, o);
            q += __shfl_xor_sync(0xFFFFFFFFu, q, o);
        }
        if (rbase == 0) {   // lanes 0..3
            int col = warp_n * 32 + (j >> 1) * 8 + cquad + (j & 1);
            atomicAdd(&gsum[col], s);
            atomicAdd(&gss[col], q);
        }
    }
}

// ---------------- fold BN1 into W2/b2 ----------------
__global__ void k_fold1(const float* __restrict__ W2, const float* __restrict__ b2,
                        const float* __restrict__ g1, const float* __restrict__ be1,
                        float invN) {
    __shared__ float a_s[128], c_s[128];
    int j = threadIdx.x;
    float mean = g_sum1[j] * invN;
    float var  = g_ss1[j] * invN - mean * mean;
    float a    = g1[j] * rsqrtf(var + BN_EPS);
    a_s[j] = a;
    c_s[j] = be1[j] - a * mean;
    __syncthreads();
    float acc = 0.f;
    for (int k = 0; k < 128; k++) {
        float w = W2[k * 128 + j];
        g_W2f[k * 128 + j] = a_s[k] * w;
        acc = fmaf(c_s[k], w, acc);
    }
    g_b2f[j] = b2[j] + acc;
}
__global__ void k_a2c2(const float* __restrict__ g2, const float* __restrict__ be2, float invN) {
    int j = threadIdx.x;
    float mean = g_sum2[j] * invN;
    float var  = g_ss2[j] * invN - mean * mean;
    float a    = g2[j] * rsqrtf(var + BN_EPS);
    g_a2[j] = a;
    g_c2[j] = be2[j] - a * mean;
}
__global__ void k_bn2(float4* __restrict__ Y, int n4) {
    int stride = gridDim.x * blockDim.x;
    for (int i = blockIdx.x * blockDim.x + threadIdx.x; i < n4; i += stride) {
        int c4 = i & 31;
        float4 v = Y[i];
        float4 a = __ldg((const float4*)g_a2 + c4);
        float4 c = __ldg((const float4*)g_c2 + c4);
        v.x = fmaf(a.x, v.x, c.x);
        v.y = fmaf(a.y, v.y, c.y);
        v.z = fmaf(a.z, v.z, c.z);
        v.w = fmaf(a.w, v.w, c.w);
        Y[i] = v;
    }
}

// ---------------- launcher ----------------
extern "C" void kernel_launch(void* const* d_in, const int* in_sizes, int n_in,
                              void* d_out, int out_size) {
    const float* x   = (const float*)d_in[0];
    const void*  eix = d_in[1];
    const float* W1  = (const float*)d_in[2];
    const float* b1  = (const float*)d_in[3];
    const float* g1  = (const float*)d_in[4];
    const float* be1 = (const float*)d_in[5];
    const float* W2  = (const float*)d_in[6];
    const float* b2  = (const float*)d_in[7];
    const float* g2  = (const float*)d_in[8];
    const float* be2 = (const float*)d_in[9];
    float* out = (float*)d_out;

    const int N = in_sizes[0] / 64;
    const int E = in_sizes[1] / 2;

    // smem bytes: 2 planes A (128 x (K+8)) + 2 planes W (K x 136), bf16
    const int SMEM1 = (2 * 128 * (64 + 8) + 2 * 64 * 136) * 2;     //  71 680
    const int SMEM2 = (2 * 128 * (128 + 8) + 2 * 128 * 136) * 2;   // 139 264
    cudaFuncSetAttribute(k_gemm_mma<64>,  cudaFuncAttributeMaxDynamicSharedMemorySize, SMEM1);
    cudaFuncSetAttribute(k_gemm_mma<128>, cudaFuncAttributeMaxDynamicSharedMemorySize, SMEM2);

    void *p_h0, *p_h1, *p_W2f, *p_b2f, *p_s1, *p_q1, *p_s2, *p_q2;
    cudaGetSymbolAddress(&p_h0, g_h0);
    cudaGetSymbolAddress(&p_h1, g_h1);
    cudaGetSymbolAddress(&p_W2f, g_W2f);
    cudaGetSymbolAddress(&p_b2f, g_b2f);
    cudaGetSymbolAddress(&p_s1, g_sum1);
    cudaGetSymbolAddress(&p_q1, g_ss1);
    cudaGetSymbolAddress(&p_s2, g_sum2);
    cudaGetSymbolAddress(&p_q2, g_ss2);

    const int GB = 148 * 8;
    const int ntiles = (N + 127) / 128;
    const int gb = ntiles < 148 ? ntiles : 148;
    const float invN = 1.0f / (float)N;

    k_zero_stats<<<1, 128>>>();
    k_detect<<<1, 256>>>((const int*)eix, E);
    k_copy<<<GB, 256>>>((const float4*)x, N * 16);
    k_scatter<<<GB * 2, 256>>>(eix, x, E);
    k_gemm_mma<64><<<gb, 512, SMEM1>>>(
        (const float*)p_h0, W1, b1, (float*)p_h1, N, ntiles,
        (float*)p_s1, (float*)p_q1);
    k_fold1<<<1, 128>>>(W2, b2, g1, be1, invN);
    k_gemm_mma<128><<<gb, 512, SMEM2>>>(
        (const float*)p_h1, (const float*)p_W2f, (const float*)p_b2f, out, N,
        ntiles, (float*)p_s2, (float*)p_q2);
    k_a2c2<<<1, 128>>>(g2, be2, invN);
    k_bn2<<<GB, 256>>>((float4*)out, N * 32);
}

// round 8
// speedup vs baseline: 1.6400x; 1.0023x over previous
#include <cuda_runtime.h>
#include <cuda_bf16.h>
#include <cstdint>

// ---------------- static device scratch (no allocation allowed) ----------------
#define MAXN 100000
__device__ float g_h0[MAXN * 64];                 // x + agg
__device__ __nv_bfloat16 g_h1h[MAXN * 128];       // h1 bf16 hi plane
__device__ __nv_bfloat16 g_h1l[MAXN * 128];       // h1 bf16 lo (residual) plane
__device__ float g_W2f[128 * 128];                // BN1-folded W2
__device__ float g_b2f[128];                      // BN1-folded b2
__device__ float g_sum1[128], g_ss1[128];
__device__ float g_sum2[128], g_ss2[128];
__device__ float g_a2[128], g_c2[128];
__device__ int   g_is64;

#define BN_EPS 1e-5f

// ---------------- warp-MMA helpers (base ISA, sm_80+: legal on compute_103) ----
#define LDSM4(r, a)                                                            \
    asm volatile("ldmatrix.sync.aligned.m8n8.x4.shared.b16 {%0,%1,%2,%3}, [%4];" \
                 : "=r"((r)[0]), "=r"((r)[1]), "=r"((r)[2]), "=r"((r)[3])      \
                 : "r"(a))
#define LDSM4T(r, a)                                                           \
    asm volatile("ldmatrix.sync.aligned.m8n8.x4.trans.shared.b16 {%0,%1,%2,%3}, [%4];" \
                 : "=r"((r)[0]), "=r"((r)[1]), "=r"((r)[2]), "=r"((r)[3])      \
                 : "r"(a))
#define MMA16816(d, a, b0, b1)                                                 \
    asm volatile("mma.sync.aligned.m16n8k16.row.col.f32.bf16.bf16.f32 "        \
                 "{%0,%1,%2,%3}, {%4,%5,%6,%7}, {%8,%9}, {%0,%1,%2,%3};"       \
                 : "+f"((d)[0]), "+f"((d)[1]), "+f"((d)[2]), "+f"((d)[3])      \
                 : "r"((a)[0]), "r"((a)[1]), "r"((a)[2]), "r"((a)[3]),         \
                   "r"(b0), "r"(b1))

__device__ __forceinline__ uint32_t smem_u32(const void* p) {
    return (uint32_t)__cvta_generic_to_shared(p);
}
// fp32 pair -> bf16x2 hi word + bf16x2 lo (residual) word
__device__ __forceinline__ void pack_pair(float vx, float vy, unsigned& hi, unsigned& lo) {
    __nv_bfloat16 h0 = __float2bfloat16(vx);
    __nv_bfloat16 h1 = __float2bfloat16(vy);
    __nv_bfloat16 l0 = __float2bfloat16(vx - __bfloat162float(h0));
    __nv_bfloat16 l1 = __float2bfloat16(vy - __bfloat162float(h1));
    hi = ((unsigned)__bfloat16_as_ushort(h1) << 16) | __bfloat16_as_ushort(h0);
    lo = ((unsigned)__bfloat16_as_ushort(l1) << 16) | __bfloat16_as_ushort(l0);
}

// ---------------- small pipeline kernels ----------------
__global__ void k_zero_stats() {
    int j = threadIdx.x;
    if (j < 128) { g_sum1[j] = 0.f; g_ss1[j] = 0.f; g_sum2[j] = 0.f; g_ss2[j] = 0.f; }
}
__global__ void k_detect(const int* __restrict__ idx, int n_pairs) {
    __shared__ int nz;
    if (threadIdx.x == 0) nz = 0;
    __syncthreads();
    int lim = n_pairs < 1024 ? n_pairs : 1024;
    for (int i = threadIdx.x; i < lim; i += blockDim.x)
        if (idx[2 * i + 1] != 0) nz = 1;
    __syncthreads();
    if (threadIdx.x == 0) g_is64 = (nz == 0) ? 1 : 0;
}
__global__ void k_copy(const float4* __restrict__ x, int n4) {
    float4* d = (float4*)g_h0;
    int stride = gridDim.x * blockDim.x;
    for (int i = blockIdx.x * blockDim.x + threadIdx.x; i < n4; i += stride)
        d[i] = x[i];
}
__global__ void k_scatter(const void* __restrict__ eptr, const float* __restrict__ x, int E) {
    const int is64 = g_is64;
    const long long total = (long long)E * 16;
    const long long stride = (long long)gridDim.x * blockDim.x;
    for (long long i = (long long)blockIdx.x * blockDim.x + threadIdx.x; i < total; i += stride) {
        int e = (int)(i >> 4);
        int c = (int)(i & 15);
        int src, dst;
        if (is64) {
            const long long* p = (const long long*)eptr;
            src = (int)p[e]; dst = (int)p[E + e];
        } else {
            const int* p = (const int*)eptr;
            src = p[e]; dst = p[E + e];
        }
        float4 v = __ldg((const float4*)x + (long long)src * 16 + c);
        float* d = g_h0 + (long long)dst * 64 + c * 4;
        asm volatile("red.global.add.v4.f32 [%0], {%1,%2,%3,%4};"
                     :: "l"(d), "f"(v.x), "f"(v.y), "f"(v.z), "f"(v.w) : "memory");
    }
}

// ================= GEMM1: h1 = relu(h0[N,64] @ W1 + b1), bf16-split ===========
// Output written as bf16 hi/lo planes (exact values GEMM2 needs), stats on fp32.
__global__ void __launch_bounds__(512, 1)
k_gemm1(const float* __restrict__ X, const float* __restrict__ W,
        const float* __restrict__ B, __nv_bfloat16* __restrict__ Yh,
        __nv_bfloat16* __restrict__ Yl,
        int N, int ntiles, float* __restrict__ gsum, float* __restrict__ gss) {
    constexpr int K = 64, AS = K + 8, WS = 136;
    extern __shared__ __nv_bfloat16 sm1[];
    __nv_bfloat16* a_hi = sm1;                    // 128*AS
    __nv_bfloat16* a_lo = a_hi + 128 * AS;
    __nv_bfloat16* w_hi = a_lo + 128 * AS;        // K*WS
    __nv_bfloat16* w_lo = w_hi + K * WS;

    const int tid    = threadIdx.x;
    const int wid    = tid >> 5;
    const int lane   = tid & 31;
    const int warp_m = wid & 3;
    const int warp_n = wid >> 2;

    for (int f = tid; f < K * 64; f += 512) {
        int k  = f >> 6;
        int n2 = f & 63;
        float2 wv = *(const float2*)(W + (long long)k * 128 + n2 * 2);
        unsigned hi, lo;
        pack_pair(wv.x, wv.y, hi, lo);
        *(unsigned*)(w_hi + k * WS + n2 * 2) = hi;
        *(unsigned*)(w_lo + k * WS + n2 * 2) = lo;
    }

    const int rbase = lane >> 2;
    const int cquad = (lane & 3) * 2;
    const uint32_t aoff = ((warp_m * 32 + (lane & 15)) * AS + (lane >> 4) * 8) * 2;
    const uint32_t a_hi_base = smem_u32(a_hi) + aoff;
    const uint32_t a_lo_base = smem_u32(a_lo) + aoff;
    const uint32_t woff = ((lane & 15) * WS + warp_n * 32 + (lane >> 4) * 8) * 2;
    const uint32_t w_hi_base = smem_u32(w_hi) + woff;
    const uint32_t w_lo_base = smem_u32(w_lo) + woff;

    float bias2[4][2];
#pragma unroll
    for (int ni = 0; ni < 4; ni++) {
        bias2[ni][0] = __ldg(B + warp_n * 32 + ni * 8 + cquad);
        bias2[ni][1] = __ldg(B + warp_n * 32 + ni * 8 + cquad + 1);
    }
    float csum[8], csq[8];
#pragma unroll
    for (int j = 0; j < 8; j++) { csum[j] = 0.f; csq[j] = 0.f; }

    for (int tile = blockIdx.x; tile < ntiles; tile += gridDim.x) {
        const int row0 = tile * 128;
        __syncthreads();
        for (int f = tid; f < 128 * (K / 2); f += 512) {
            int r  = f / (K / 2);
            int c2 = f % (K / 2);
            float2 v = make_float2(0.f, 0.f);
            if (row0 + r < N)
                v = *(const float2*)(X + (long long)(row0 + r) * K + c2 * 2);
            unsigned hi, lo;
            pack_pair(v.x, v.y, hi, lo);
            *(unsigned*)(a_hi + r * AS + c2 * 2) = hi;
            *(unsigned*)(a_lo + r * AS + c2 * 2) = lo;
        }
        __syncthreads();

        float acc[2][4][4];
#pragma unroll
        for (int mi = 0; mi < 2; mi++)
#pragma unroll
            for (int ni = 0; ni < 4; ni++)
#pragma unroll
                for (int q = 0; q < 4; q++) acc[mi][ni][q] = 0.f;

#pragma unroll
        for (int k0 = 0; k0 < K; k0 += 16) {
            uint32_t ah[2][4], al[2][4];
            LDSM4(ah[0], a_hi_base + (0 * 16 * AS + k0) * 2);
            LDSM4(ah[1], a_hi_base + (1 * 16 * AS + k0) * 2);
            LDSM4(al[0], a_lo_base + (0 * 16 * AS + k0) * 2);
            LDSM4(al[1], a_lo_base + (1 * 16 * AS + k0) * 2);
            uint32_t bh0[4], bh1[4], bl0[4], bl1[4];
            LDSM4T(bh0, w_hi_base + (k0 * WS + 0) * 2);
            LDSM4T(bh1, w_hi_base + (k0 * WS + 16) * 2);
            LDSM4T(bl0, w_lo_base + (k0 * WS + 0) * 2);
            LDSM4T(bl1, w_lo_base + (k0 * WS + 16) * 2);
#pragma unroll
            for (int mi = 0; mi < 2; mi++) {
                MMA16816(acc[mi][0], ah[mi], bh0[0], bh0[1]);
                MMA16816(acc[mi][1], ah[mi], bh0[2], bh0[3]);
                MMA16816(acc[mi][2], ah[mi], bh1[0], bh1[1]);
                MMA16816(acc[mi][3], ah[mi], bh1[2], bh1[3]);
                MMA16816(acc[mi][0], ah[mi], bl0[0], bl0[1]);
                MMA16816(acc[mi][1], ah[mi], bl0[2], bl0[3]);
                MMA16816(acc[mi][2], ah[mi], bl1[0], bl1[1]);
                MMA16816(acc[mi][3], ah[mi], bl1[2], bl1[3]);
                MMA16816(acc[mi][0], al[mi], bh0[0], bh0[1]);
                MMA16816(acc[mi][1], al[mi], bh0[2], bh0[3]);
                MMA16816(acc[mi][2], al[mi], bh1[0], bh1[1]);
                MMA16816(acc[mi][3], al[mi], bh1[2], bh1[3]);
            }
        }

        // epilogue: bias + relu + stats + pack to bf16 planes
#pragma unroll
        for (int mi = 0; mi < 2; mi++) {
#pragma unroll
            for (int ri = 0; ri < 2; ri++) {
                int row = row0 + warp_m * 32 + mi * 16 + ri * 8 + rbase;
                if (row < N) {
                    long long rb = (long long)row * 128 + warp_n * 32;
#pragma unroll
                    for (int ni = 0; ni < 4; ni++) {
                        float o0 = fmaxf(acc[mi][ni][ri * 2 + 0] + bias2[ni][0], 0.f);
                        float o1 = fmaxf(acc[mi][ni][ri * 2 + 1] + bias2[ni][1], 0.f);
                        csum[ni * 2 + 0] += o0;
                        csum[ni * 2 + 1] += o1;
                        csq[ni * 2 + 0] = fmaf(o0, o0, csq[ni * 2 + 0]);
                        csq[ni * 2 + 1] = fmaf(o1, o1, csq[ni * 2 + 1]);
                        unsigned hi, lo;
                        pack_pair(o0, o1, hi, lo);
                        *(unsigned*)(Yh + rb + ni * 8 + cquad) = hi;
                        *(unsigned*)(Yl + rb + ni * 8 + cquad) = lo;
                    }
                }
            }
        }
    }

#pragma unroll
    for (int j = 0; j < 8; j++) {
        float s = csum[j], q = csq[j];
#pragma unroll
        for (int o = 4; o <= 16; o <<= 1) {
            s += __shfl_xor_sync(0xFFFFFFFFu, s, o);
            q += __shfl_xor_sync(0xFFFFFFFFu, q, o);
        }
        if (rbase == 0) {
            int col = warp_n * 32 + (j >> 1) * 8 + cquad + (j & 1);
            atomicAdd(&gsum[col], s);
            atomicAdd(&gss[col], q);
        }
    }
}

// ================= GEMM2: out = relu(h1[N,128] @ W2f + b2f), cp.async dbuf =====
// A already bf16 hi/lo in global planes -> staging is pure async 16B copies.
__global__ void __launch_bounds__(512, 1)
k_gemm2(const __nv_bfloat16* __restrict__ Xh, const __nv_bfloat16* __restrict__ Xl,
        const float* __restrict__ W, const float* __restrict__ B,
        float* __restrict__ Y, int N, int ntiles,
        float* __restrict__ gsum, float* __restrict__ gss) {
    constexpr int K = 128, AS = 136, WS = 136;
    extern __shared__ __nv_bfloat16 sm2[];
    __nv_bfloat16* w_hi = sm2;                    // K*WS
    __nv_bfloat16* w_lo = w_hi + K * WS;
    __nv_bfloat16* a0h  = w_lo + K * WS;          // 128*AS each
    __nv_bfloat16* a0l  = a0h + 128 * AS;
    __nv_bfloat16* a1h  = a0l + 128 * AS;
    __nv_bfloat16* a1l  = a1h + 128 * AS;

    const int tid    = threadIdx.x;
    const int wid    = tid >> 5;
    const int lane   = tid & 31;
    const int warp_m = wid & 3;
    const int warp_n = wid >> 2;

    // stage W (fp32 -> hi/lo) once
    for (int f = tid; f < K * 64; f += 512) {
        int k  = f >> 6;
        int n2 = f & 63;
        float2 wv = *(const float2*)(W + (long long)k * 128 + n2 * 2);
        unsigned hi, lo;
        pack_pair(wv.x, wv.y, hi, lo);
        *(unsigned*)(w_hi + k * WS + n2 * 2) = hi;
        *(unsigned*)(w_lo + k * WS + n2 * 2) = lo;
    }

    // async tile stage: 4096 16B chunks (128 rows x 16 segs x 2 planes)
    auto issue_tile = [&](int t, __nv_bfloat16* dh, __nv_bfloat16* dl) {
#pragma unroll
        for (int i = 0; i < 8; i++) {
            int f   = tid + i * 512;
            int r   = f >> 5;
            int rem = f & 31;
            int pl  = rem >> 4;
            int seg = rem & 15;
            int row = t * 128 + r;
            int rc  = row < N ? row : (N - 1);
            const __nv_bfloat16* src = (pl ? Xl : Xh) + (long long)rc * 128 + seg * 8;
            unsigned sa = smem_u32((pl ? dl : dh) + r * AS + seg * 8);
            int bytes = (row < N) ? 16 : 0;
            asm volatile("cp.async.cg.shared.global [%0], [%1], 16, %2;"
                         :: "r"(sa), "l"(src), "r"(bytes));
        }
        asm volatile("cp.async.commit_group;");
    };

    const int rbase = lane >> 2;
    const int cquad = (lane & 3) * 2;
    const uint32_t aoff = ((warp_m * 32 + (lane & 15)) * AS + (lane >> 4) * 8) * 2;
    const uint32_t woff = ((lane & 15) * WS + warp_n * 32 + (lane >> 4) * 8) * 2;
    const uint32_t w_hi_base = smem_u32(w_hi) + woff;
    const uint32_t w_lo_base = smem_u32(w_lo) + woff;
    const uint32_t a_bases[2][2] = {
        { smem_u32(a0h) + aoff, smem_u32(a0l) + aoff },
        { smem_u32(a1h) + aoff, smem_u32(a1l) + aoff } };

    float bias2[4][2];
#pragma unroll
    for (int ni = 0; ni < 4; ni++) {
        bias2[ni][0] = __ldg(B + warp_n * 32 + ni * 8 + cquad);
        bias2[ni][1] = __ldg(B + warp_n * 32 + ni * 8 + cquad + 1);
    }
    float csum[8], csq[8];
#pragma unroll
    for (int j = 0; j < 8; j++) { csum[j] = 0.f; csq[j] = 0.f; }

    int p = 0;
    int tile = blockIdx.x;
    if (tile < ntiles) issue_tile(tile, a0h, a0l);

    for (; tile < ntiles; tile += gridDim.x) {
        const int row0 = tile * 128;
        int tnext = tile + gridDim.x;
        if (tnext < ntiles) {
            issue_tile(tnext, p ? a0h : a1h, p ? a0l : a1l);
            asm volatile("cp.async.wait_group 1;");
        } else {
            asm volatile("cp.async.wait_group 0;");
        }
        __syncthreads();

        const uint32_t a_hi_base = a_bases[p][0];
        const uint32_t a_lo_base = a_bases[p][1];

        float acc[2][4][4];
#pragma unroll
        for (int mi = 0; mi < 2; mi++)
#pragma unroll
            for (int ni = 0; ni < 4; ni++)
#pragma unroll
                for (int q = 0; q < 4; q++) acc[mi][ni][q] = 0.f;

#pragma unroll
        for (int k0 = 0; k0 < K; k0 += 16) {
            uint32_t ah[2][4], al[2][4];
            LDSM4(ah[0], a_hi_base + (0 * 16 * AS + k0) * 2);
            LDSM4(ah[1], a_hi_base + (1 * 16 * AS + k0) * 2);
            LDSM4(al[0], a_lo_base + (0 * 16 * AS + k0) * 2);
            LDSM4(al[1], a_lo_base + (1 * 16 * AS + k0) * 2);
            uint32_t bh0[4], bh1[4], bl0[4], bl1[4];
            LDSM4T(bh0, w_hi_base + (k0 * WS + 0) * 2);
            LDSM4T(bh1, w_hi_base + (k0 * WS + 16) * 2);
            LDSM4T(bl0, w_lo_base + (k0 * WS + 0) * 2);
            LDSM4T(bl1, w_lo_base + (k0 * WS + 16) * 2);
#pragma unroll
            for (int mi = 0; mi < 2; mi++) {
                MMA16816(acc[mi][0], ah[mi], bh0[0], bh0[1]);
                MMA16816(acc[mi][1], ah[mi], bh0[2], bh0[3]);
                MMA16816(acc[mi][2], ah[mi], bh1[0], bh1[1]);
                MMA16816(acc[mi][3], ah[mi], bh1[2], bh1[3]);
                MMA16816(acc[mi][0], ah[mi], bl0[0], bl0[1]);
                MMA16816(acc[mi][1], ah[mi], bl0[2], bl0[3]);
                MMA16816(acc[mi][2], ah[mi], bl1[0], bl1[1]);
                MMA16816(acc[mi][3], ah[mi], bl1[2], bl1[3]);
                MMA16816(acc[mi][0], al[mi], bh0[0], bh0[1]);
                MMA16816(acc[mi][1], al[mi], bh0[2], bh0[3]);
                MMA16816(acc[mi][2], al[mi], bh1[0], bh1[1]);
                MMA16816(acc[mi][3], al[mi], bh1[2], bh1[3]);
            }
        }

        // epilogue: bias + relu + stats + fp32 store
#pragma unroll
        for (int mi = 0; mi < 2; mi++) {
#pragma unroll
            for (int ri = 0; ri < 2; ri++) {
                int row = row0 + warp_m * 32 + mi * 16 + ri * 8 + rbase;
                if (row < N) {
                    float* yr = Y + (long long)row * 128 + warp_n * 32;
#pragma unroll
                    for (int ni = 0; ni < 4; ni++) {
                        float o0 = fmaxf(acc[mi][ni][ri * 2 + 0] + bias2[ni][0], 0.f);
                        float o1 = fmaxf(acc[mi][ni][ri * 2 + 1] + bias2[ni][1], 0.f);
                        csum[ni * 2 + 0] += o0;
                        csum[ni * 2 + 1] += o1;
                        csq[ni * 2 + 0] = fmaf(o0, o0, csq[ni * 2 + 0]);
                        csq[ni * 2 + 1] = fmaf(o1, o1, csq[ni * 2 + 1]);
                        *(float2*)(yr + ni * 8 + cquad) = make_float2(o0, o1);
                    }
                }
            }
        }
        __syncthreads();
        p ^= 1;
    }

#pragma unroll
    for (int j = 0; j < 8; j++) {
        float s = csum[j], q = csq[j];
#pragma unroll
        for (int o = 4; o <= 16; o <<= 1) {
            s += __shfl_xor_sync(0xFFFFFFFFu, s, o);
            q += __shfl_xor_sync(0xFFFFFFFFu, q, o);
        }
        if (rbase == 0) {
            int col = warp_n * 32 + (j >> 1) * 8 + cquad + (j & 1);
            atomicAdd(&gsum[col], s);
            atomicAdd(&gss[col], q);
        }
    }
}

// ---------------- fold BN1 into W2/b2 ----------------
__global__ void k_fold1(const float* __restrict__ W2, const float* __restrict__ b2,
                        const float* __restrict__ g1, const float* __restrict__ be1,
                        float invN) {
    __shared__ float a_s[128], c_s[128];
    int j = threadIdx.x;
    float mean = g_sum1[j] * invN;
    float var  = g_ss1[j] * invN - mean * mean;
    float a    = g1[j] * rsqrtf(var + BN_EPS);
    a_s[j] = a;
    c_s[j] = be1[j] - a * mean;
    __syncthreads();
    float acc = 0.f;
    for (int k = 0; k < 128; k++) {
        float w = W2[k * 128 + j];
        g_W2f[k * 128 + j] = a_s[k] * w;
        acc = fmaf(c_s[k], w, acc);
    }
    g_b2f[j] = b2[j] + acc;
}
__global__ void k_a2c2(const float* __restrict__ g2, const float* __restrict__ be2, float invN) {
    int j = threadIdx.x;
    float mean = g_sum2[j] * invN;
    float var  = g_ss2[j] * invN - mean * mean;
    float a    = g2[j] * rsqrtf(var + BN_EPS);
    g_a2[j] = a;
    g_c2[j] = be2[j] - a * mean;
}
__global__ void k_bn2(float4* __restrict__ Y, int n4) {
    int stride = gridDim.x * blockDim.x;
    for (int i = blockIdx.x * blockDim.x + threadIdx.x; i < n4; i += stride) {
        int c4 = i & 31;
        float4 v = Y[i];
        float4 a = __ldg((const float4*)g_a2 + c4);
        float4 c = __ldg((const float4*)g_c2 + c4);
        v.x = fmaf(a.x, v.x, c.x);
        v.y = fmaf(a.y, v.y, c.y);
        v.z = fmaf(a.z, v.z, c.z);
        v.w = fmaf(a.w, v.w, c.w);
        Y[i] = v;
    }
}

// ---------------- launcher ----------------
extern "C" void kernel_launch(void* const* d_in, const int* in_sizes, int n_in,
                              void* d_out, int out_size) {
    const float* x   = (const float*)d_in[0];
    const void*  eix = d_in[1];
    const float* W1  = (const float*)d_in[2];
    const float* b1  = (const float*)d_in[3];
    const float* g1  = (const float*)d_in[4];
    const float* be1 = (const float*)d_in[5];
    const float* W2  = (const float*)d_in[6];
    const float* b2  = (const float*)d_in[7];
    const float* g2  = (const float*)d_in[8];
    const float* be2 = (const float*)d_in[9];
    float* out = (float*)d_out;

    const int N = in_sizes[0] / 64;
    const int E = in_sizes[1] / 2;

    const int SMEM1 = (2 * 128 * 72 + 2 * 64 * 136) * 2;     //  71 680
    const int SMEM2 = (2 * 128 * 136 + 4 * 128 * 136) * 2;   // 208 896
    cudaFuncSetAttribute(k_gemm1, cudaFuncAttributeMaxDynamicSharedMemorySize, SMEM1);
    cudaFuncSetAttribute(k_gemm2, cudaFuncAttributeMaxDynamicSharedMemorySize, SMEM2);

    void *p_h0, *p_h1h, *p_h1l, *p_W2f, *p_b2f, *p_s1, *p_q1, *p_s2, *p_q2;
    cudaGetSymbolAddress(&p_h0, g_h0);
    cudaGetSymbolAddress(&p_h1h, g_h1h);
    cudaGetSymbolAddress(&p_h1l, g_h1l);
    cudaGetSymbolAddress(&p_W2f, g_W2f);
    cudaGetSymbolAddress(&p_b2f, g_b2f);
    cudaGetSymbolAddress(&p_s1, g_sum1);
    cudaGetSymbolAddress(&p_q1, g_ss1);
    cudaGetSymbolAddress(&p_s2, g_sum2);
    cudaGetSymbolAddress(&p_q2, g_ss2);

    const int GB = 148 * 8;
    const int ntiles = (N + 127) / 128;
    const int gb = ntiles < 148 ? ntiles : 148;
    const float invN = 1.0f / (float)N;

    k_zero_stats<<<1, 128>>>();
    k_detect<<<1, 256>>>((const int*)eix, E);
    k_copy<<<GB, 256>>>((const float4*)x, N * 16);
    k_scatter<<<GB * 2, 256>>>(eix, x, E);
    k_gemm1<<<gb, 512, SMEM1>>>(
        (const float*)p_h0, W1, b1, (__nv_bfloat16*)p_h1h, (__nv_bfloat16*)p_h1l,
        N, ntiles, (float*)p_s1, (float*)p_q1);
    k_fold1<<<1, 128>>>(W2, b2, g1, be1, invN);
    k_gemm2<<<gb, 512, SMEM2>>>(
        (const __nv_bfloat16*)p_h1h, (const __nv_bfloat16*)p_h1l,
        (const float*)p_W2f, (const float*)p_b2f, out, N, ntiles,
        (float*)p_s2, (float*)p_q2);
    k_a2c2<<<1, 128>>>(g2, be2, invN);
    k_bn2<<<GB, 256>>>((float4*)out, N * 32);
}

// round 9
// speedup vs baseline: 1.7154x; 1.0460x over previous
#include <cuda_runtime.h>
#include <cuda_bf16.h>
#include <cstdint>

// ---------------- static device scratch (no allocation allowed) ----------------
#define MAXN 100000
#define MAXE 1600000
__device__ __nv_bfloat16 g_h0h[MAXN * 64];        // h0 = x+agg, bf16 hi plane
__device__ __nv_bfloat16 g_h0l[MAXN * 64];        // h0 bf16 lo (residual) plane
__device__ __nv_bfloat16 g_h1h[MAXN * 128];       // h1 bf16 hi plane
__device__ __nv_bfloat16 g_h1l[MAXN * 128];       // h1 bf16 lo plane
__device__ float g_W2f[128 * 128];                // BN1-folded W2
__device__ float g_b2f[128];                      // BN1-folded b2
__device__ float g_sum1[128], g_ss1[128];
__device__ float g_sum2[128], g_ss2[128];
__device__ float g_a2[128], g_c2[128];
__device__ int   g_is64;
// CSR scratch
__device__ int g_cnt[MAXN];          // histogram, then cursor
__device__ int g_off[MAXN + 1];      // offsets
__device__ int g_perm[MAXE];         // src list grouped by dst
__device__ int g_blk[512];           // scan block sums
__device__ int g_blkscan[512];

#define BN_EPS 1e-5f

// ---------------- warp-MMA helpers (base ISA, sm_80+) ----------------
#define LDSM4(r, a)                                                            \
    asm volatile("ldmatrix.sync.aligned.m8n8.x4.shared.b16 {%0,%1,%2,%3}, [%4];" \
                 : "=r"((r)[0]), "=r"((r)[1]), "=r"((r)[2]), "=r"((r)[3])      \
                 : "r"(a))
#define LDSM4T(r, a)                                                           \
    asm volatile("ldmatrix.sync.aligned.m8n8.x4.trans.shared.b16 {%0,%1,%2,%3}, [%4];" \
                 : "=r"((r)[0]), "=r"((r)[1]), "=r"((r)[2]), "=r"((r)[3])      \
                 : "r"(a))
#define MMA16816(d, a, b0, b1)                                                 \
    asm volatile("mma.sync.aligned.m16n8k16.row.col.f32.bf16.bf16.f32 "        \
                 "{%0,%1,%2,%3}, {%4,%5,%6,%7}, {%8,%9}, {%0,%1,%2,%3};"       \
                 : "+f"((d)[0]), "+f"((d)[1]), "+f"((d)[2]), "+f"((d)[3])      \
                 : "r"((a)[0]), "r"((a)[1]), "r"((a)[2]), "r"((a)[3]),         \
                   "r"(b0), "r"(b1))

__device__ __forceinline__ uint32_t smem_u32(const void* p) {
    return (uint32_t)__cvta_generic_to_shared(p);
}
__device__ __forceinline__ void pack_pair(float vx, float vy, unsigned& hi, unsigned& lo) {
    __nv_bfloat16 h0 = __float2bfloat16(vx);
    __nv_bfloat16 h1 = __float2bfloat16(vy);
    __nv_bfloat16 l0 = __float2bfloat16(vx - __bfloat162float(h0));
    __nv_bfloat16 l1 = __float2bfloat16(vy - __bfloat162float(h1));
    hi = ((unsigned)__bfloat16_as_ushort(h1) << 16) | __bfloat16_as_ushort(h0);
    lo = ((unsigned)__bfloat16_as_ushort(l1) << 16) | __bfloat16_as_ushort(l0);
}

// ---------------- pipeline prep kernels ----------------
__global__ void k_zero(int N) {
    int stride = gridDim.x * blockDim.x;
    int i = blockIdx.x * blockDim.x + threadIdx.x;
    if (i < 128) { g_sum1[i] = 0.f; g_ss1[i] = 0.f; g_sum2[i] = 0.f; g_ss2[i] = 0.f; }
    for (; i < N; i += stride) g_cnt[i] = 0;
}
__global__ void k_detect(const int* __restrict__ idx, int n_pairs) {
    __shared__ int nz;
    if (threadIdx.x == 0) nz = 0;
    __syncthreads();
    int lim = n_pairs < 1024 ? n_pairs : 1024;
    for (int i = threadIdx.x; i < lim; i += blockDim.x)
        if (idx[2 * i + 1] != 0) nz = 1;
    __syncthreads();
    if (threadIdx.x == 0) g_is64 = (nz == 0) ? 1 : 0;
}
__global__ void k_hist(const void* __restrict__ eptr, int E) {
    const int is64 = g_is64;
    int stride = gridDim.x * blockDim.x;
    for (int e = blockIdx.x * blockDim.x + threadIdx.x; e < E; e += stride) {
        int dst = is64 ? (int)((const long long*)eptr)[E + e] : ((const int*)eptr)[E + e];
        atomicAdd(&g_cnt[dst], 1);
    }
}
// exclusive scan of g_cnt[0..N) -> g_off, 3 phases
__global__ void k_scanA(int N) {
    __shared__ int s[512];
    int tid = threadIdx.x;
    int i = blockIdx.x * 512 + tid;
    int v = (i < N) ? g_cnt[i] : 0;
    s[tid] = v;
    __syncthreads();
    for (int o = 1; o < 512; o <<= 1) {
        int t = (tid >= o) ? s[tid - o] : 0;
        __syncthreads();
        s[tid] += t;
        __syncthreads();
    }
    if (i < N) g_off[i] = s[tid] - v;       // block-local exclusive
    if (tid == 511) g_blk[blockIdx.x] = s[511];
}
__global__ void k_scanB(int nb) {
    __shared__ int s[512];
    int tid = threadIdx.x;
    int v = (tid < nb) ? g_blk[tid] : 0;
    s[tid] = v;
    __syncthreads();
    for (int o = 1; o < 512; o <<= 1) {
        int t = (tid >= o) ? s[tid - o] : 0;
        __syncthreads();
        s[tid] += t;
        __syncthreads();
    }
    if (tid < nb) g_blkscan[tid] = s[tid] - v;   // exclusive block offsets
}
__global__ void k_scanC(int N, int E) {
    int stride = gridDim.x * blockDim.x;
    for (int i = blockIdx.x * blockDim.x + threadIdx.x; i < N; i += stride) {
        int o = g_off[i] + g_blkscan[i >> 9];
        g_off[i] = o;
        g_cnt[i] = o;                        // cursor init
    }
    if (blockIdx.x == 0 && threadIdx.x == 0) g_off[N] = E;
}
__global__ void k_permute(const void* __restrict__ eptr, int E) {
    const int is64 = g_is64;
    int stride = gridDim.x * blockDim.x;
    for (int e = blockIdx.x * blockDim.x + threadIdx.x; e < E; e += stride) {
        int src, dst;
        if (is64) {
            const long long* p = (const long long*)eptr;
            src = (int)p[e]; dst = (int)p[E + e];
        } else {
            const int* p = (const int*)eptr;
            src = p[e]; dst = p[E + e];
        }
        int pos = atomicAdd(&g_cnt[dst], 1);
        g_perm[pos] = src;
    }
}

// ---------------- warp-per-dst aggregation: h0 = x[d] + sum x[src], to bf16 planes ----
__global__ void __launch_bounds__(512, 1)
k_aggregate(const float* __restrict__ x, int N) {
    const int lane = threadIdx.x & 31;
    const int wglb = (blockIdx.x * blockDim.x + threadIdx.x) >> 5;
    const int nwarp = (gridDim.x * blockDim.x) >> 5;
    const float2* x2 = (const float2*)x;

    for (int d = wglb; d < N; d += nwarp) {
        int beg = g_off[d], end = g_off[d + 1];
        float2 s = __ldg(x2 + (long long)d * 32 + lane);
        int e = beg;
        for (; e + 1 < end; e += 2) {
            int s0 = __ldg(g_perm + e);
            int s1 = __ldg(g_perm + e + 1);
            float2 v0 = __ldg(x2 + (long long)s0 * 32 + lane);
            float2 v1 = __ldg(x2 + (long long)s1 * 32 + lane);
            s.x += v0.x; s.y += v0.y;
            s.x += v1.x; s.y += v1.y;
        }
        if (e < end) {
            int s0 = __ldg(g_perm + e);
            float2 v0 = __ldg(x2 + (long long)s0 * 32 + lane);
            s.x += v0.x; s.y += v0.y;
        }
        unsigned hi, lo;
        pack_pair(s.x, s.y, hi, lo);
        *(unsigned*)(g_h0h + (long long)d * 64 + lane * 2) = hi;
        *(unsigned*)(g_h0l + (long long)d * 64 + lane * 2) = lo;
    }
}

// ================= GEMM1: h1 = relu(h0 @ W1 + b1), cp.async dbuf, K=64 =========
__global__ void __launch_bounds__(512, 1)
k_gemm1(const __nv_bfloat16* __restrict__ Xh, const __nv_bfloat16* __restrict__ Xl,
        const float* __restrict__ W, const float* __restrict__ B,
        __nv_bfloat16* __restrict__ Yh, __nv_bfloat16* __restrict__ Yl,
        int N, int ntiles, float* __restrict__ gsum, float* __restrict__ gss) {
    constexpr int K = 64, AS = 72, WS = 136;
    extern __shared__ __nv_bfloat16 sm1[];
    __nv_bfloat16* w_hi = sm1;                    // K*WS
    __nv_bfloat16* w_lo = w_hi + K * WS;
    __nv_bfloat16* a0h  = w_lo + K * WS;          // 128*AS each
    __nv_bfloat16* a0l  = a0h + 128 * AS;
    __nv_bfloat16* a1h  = a0l + 128 * AS;
    __nv_bfloat16* a1l  = a1h + 128 * AS;

    const int tid    = threadIdx.x;
    const int wid    = tid >> 5;
    const int lane   = tid & 31;
    const int warp_m = wid & 3;
    const int warp_n = wid >> 2;

    for (int f = tid; f < K * 64; f += 512) {
        int k  = f >> 6;
        int n2 = f & 63;
        float2 wv = *(const float2*)(W + (long long)k * 128 + n2 * 2);
        unsigned hi, lo;
        pack_pair(wv.x, wv.y, hi, lo);
        *(unsigned*)(w_hi + k * WS + n2 * 2) = hi;
        *(unsigned*)(w_lo + k * WS + n2 * 2) = lo;
    }

    // tile stage: 2048 16B chunks (128 rows x 8 segs x 2 planes)
    auto issue_tile = [&](int t, __nv_bfloat16* dh, __nv_bfloat16* dl) {
#pragma unroll
        for (int i = 0; i < 4; i++) {
            int f   = tid + i * 512;
            int r   = f >> 4;
            int rem = f & 15;
            int pl  = rem >> 3;
            int seg = rem & 7;
            int row = t * 128 + r;
            int rc  = row < N ? row : (N - 1);
            const __nv_bfloat16* src = (pl ? Xl : Xh) + (long long)rc * 64 + seg * 8;
            unsigned sa = smem_u32((pl ? dl : dh) + r * AS + seg * 8);
            int bytes = (row < N) ? 16 : 0;
            asm volatile("cp.async.cg.shared.global [%0], [%1], 16, %2;"
                         :: "r"(sa), "l"(src), "r"(bytes));
        }
        asm volatile("cp.async.commit_group;");
    };

    const int rbase = lane >> 2;
    const int cquad = (lane & 3) * 2;
    const uint32_t aoff = ((warp_m * 32 + (lane & 15)) * AS + (lane >> 4) * 8) * 2;
    const uint32_t woff = ((lane & 15) * WS + warp_n * 32 + (lane >> 4) * 8) * 2;
    const uint32_t w_hi_base = smem_u32(w_hi) + woff;
    const uint32_t w_lo_base = smem_u32(w_lo) + woff;
    const uint32_t a_bases[2][2] = {
        { smem_u32(a0h) + aoff, smem_u32(a0l) + aoff },
        { smem_u32(a1h) + aoff, smem_u32(a1l) + aoff } };

    float bias2[4][2];
#pragma unroll
    for (int ni = 0; ni < 4; ni++) {
        bias2[ni][0] = __ldg(B + warp_n * 32 + ni * 8 + cquad);
        bias2[ni][1] = __ldg(B + warp_n * 32 + ni * 8 + cquad + 1);
    }
    float csum[8], csq[8];
#pragma unroll
    for (int j = 0; j < 8; j++) { csum[j] = 0.f; csq[j] = 0.f; }

    int p = 0;
    int tile = blockIdx.x;
    if (tile < ntiles) issue_tile(tile, a0h, a0l);

    for (; tile < ntiles; tile += gridDim.x) {
        const int row0 = tile * 128;
        int tnext = tile + gridDim.x;
        if (tnext < ntiles) {
            issue_tile(tnext, p ? a0h : a1h, p ? a0l : a1l);
            asm volatile("cp.async.wait_group 1;");
        } else {
            asm volatile("cp.async.wait_group 0;");
        }
        __syncthreads();

        const uint32_t a_hi_base = a_bases[p][0];
        const uint32_t a_lo_base = a_bases[p][1];

        float acc[2][4][4];
#pragma unroll
        for (int mi = 0; mi < 2; mi++)
#pragma unroll
            for (int ni = 0; ni < 4; ni++)
#pragma unroll
                for (int q = 0; q < 4; q++) acc[mi][ni][q] = 0.f;

#pragma unroll
        for (int k0 = 0; k0 < K; k0 += 16) {
            uint32_t ah[2][4], al[2][4];
            LDSM4(ah[0], a_hi_base + (0 * 16 * AS + k0) * 2);
            LDSM4(ah[1], a_hi_base + (1 * 16 * AS + k0) * 2);
            LDSM4(al[0], a_lo_base + (0 * 16 * AS + k0) * 2);
            LDSM4(al[1], a_lo_base + (1 * 16 * AS + k0) * 2);
            uint32_t bh0[4], bh1[4], bl0[4], bl1[4];
            LDSM4T(bh0, w_hi_base + (k0 * WS + 0) * 2);
            LDSM4T(bh1, w_hi_base + (k0 * WS + 16) * 2);
            LDSM4T(bl0, w_lo_base + (k0 * WS + 0) * 2);
            LDSM4T(bl1, w_lo_base + (k0 * WS + 16) * 2);
#pragma unroll
            for (int mi = 0; mi < 2; mi++) {
                MMA16816(acc[mi][0], ah[mi], bh0[0], bh0[1]);
                MMA16816(acc[mi][1], ah[mi], bh0[2], bh0[3]);
                MMA16816(acc[mi][2], ah[mi], bh1[0], bh1[1]);
                MMA16816(acc[mi][3], ah[mi], bh1[2], bh1[3]);
                MMA16816(acc[mi][0], ah[mi], bl0[0], bl0[1]);
                MMA16816(acc[mi][1], ah[mi], bl0[2], bl0[3]);
                MMA16816(acc[mi][2], ah[mi], bl1[0], bl1[1]);
                MMA16816(acc[mi][3], ah[mi], bl1[2], bl1[3]);
                MMA16816(acc[mi][0], al[mi], bh0[0], bh0[1]);
                MMA16816(acc[mi][1], al[mi], bh0[2], bh0[3]);
                MMA16816(acc[mi][2], al[mi], bh1[0], bh1[1]);
                MMA16816(acc[mi][3], al[mi], bh1[2], bh1[3]);
            }
        }

#pragma unroll
        for (int mi = 0; mi < 2; mi++) {
#pragma unroll
            for (int ri = 0; ri < 2; ri++) {
                int row = row0 + warp_m * 32 + mi * 16 + ri * 8 + rbase;
                if (row < N) {
                    long long rb = (long long)row * 128 + warp_n * 32;
#pragma unroll
                    for (int ni = 0; ni < 4; ni++) {
                        float o0 = fmaxf(acc[mi][ni][ri * 2 + 0] + bias2[ni][0], 0.f);
                        float o1 = fmaxf(acc[mi][ni][ri * 2 + 1] + bias2[ni][1], 0.f);
                        csum[ni * 2 + 0] += o0;
                        csum[ni * 2 + 1] += o1;
                        csq[ni * 2 + 0] = fmaf(o0, o0, csq[ni * 2 + 0]);
                        csq[ni * 2 + 1] = fmaf(o1, o1, csq[ni * 2 + 1]);
                        unsigned hi, lo;
                        pack_pair(o0, o1, hi, lo);
                        *(unsigned*)(Yh + rb + ni * 8 + cquad) = hi;
                        *(unsigned*)(Yl + rb + ni * 8 + cquad) = lo;
                    }
                }
            }
        }
        __syncthreads();
        p ^= 1;
    }

#pragma unroll
    for (int j = 0; j < 8; j++) {
        float s = csum[j], q = csq[j];
#pragma unroll
        for (int o = 4; o <= 16; o <<= 1) {
            s += __shfl_xor_sync(0xFFFFFFFFu, s, o);
            q += __shfl_xor_sync(0xFFFFFFFFu, q, o);
        }
        if (rbase == 0) {
            int col = warp_n * 32 + (j >> 1) * 8 + cquad + (j & 1);
            atomicAdd(&gsum[col], s);
            atomicAdd(&gss[col], q);
        }
    }
}

// ================= GEMM2: out = relu(h1 @ W2f + b2f), cp.async dbuf, K=128 =====
__global__ void __launch_bounds__(512, 1)
k_gemm2(const __nv_bfloat16* __restrict__ Xh, const __nv_bfloat16* __restrict__ Xl,
        const float* __restrict__ W, const float* __restrict__ B,
        float* __restrict__ Y, int N, int ntiles,
        float* __restrict__ gsum, float* __restrict__ gss) {
    constexpr int K = 128, AS = 136, WS = 136;
    extern __shared__ __nv_bfloat16 sm2[];
    __nv_bfloat16* w_hi = sm2;
    __nv_bfloat16* w_lo = w_hi + K * WS;
    __nv_bfloat16* a0h  = w_lo + K * WS;
    __nv_bfloat16* a0l  = a0h + 128 * AS;
    __nv_bfloat16* a1h  = a0l + 128 * AS;
    __nv_bfloat16* a1l  = a1h + 128 * AS;

    const int tid    = threadIdx.x;
    const int wid    = tid >> 5;
    const int lane   = tid & 31;
    const int warp_m = wid & 3;
    const int warp_n = wid >> 2;

    for (int f = tid; f < K * 64; f += 512) {
        int k  = f >> 6;
        int n2 = f & 63;
        float2 wv = *(const float2*)(W + (long long)k * 128 + n2 * 2);
        unsigned hi, lo;
        pack_pair(wv.x, wv.y, hi, lo);
        *(unsigned*)(w_hi + k * WS + n2 * 2) = hi;
        *(unsigned*)(w_lo + k * WS + n2 * 2) = lo;
    }

    auto issue_tile = [&](int t, __nv_bfloat16* dh, __nv_bfloat16* dl) {
#pragma unroll
        for (int i = 0; i < 8; i++) {
            int f   = tid + i * 512;
            int r   = f >> 5;
            int rem = f & 31;
            int pl  = rem >> 4;
            int seg = rem & 15;
            int row = t * 128 + r;
            int rc  = row < N ? row : (N - 1);
            const __nv_bfloat16* src = (pl ? Xl : Xh) + (long long)rc * 128 + seg * 8;
            unsigned sa = smem_u32((pl ? dl : dh) + r * AS + seg * 8);
            int bytes = (row < N) ? 16 : 0;
            asm volatile("cp.async.cg.shared.global [%0], [%1], 16, %2;"
                         :: "r"(sa), "l"(src), "r"(bytes));
        }
        asm volatile("cp.async.commit_group;");
    };

    const int rbase = lane >> 2;
    const int cquad = (lane & 3) * 2;
    const uint32_t aoff = ((warp_m * 32 + (lane & 15)) * AS + (lane >> 4) * 8) * 2;
    const uint32_t woff = ((lane & 15) * WS + warp_n * 32 + (lane >> 4) * 8) * 2;
    const uint32_t w_hi_base = smem_u32(w_hi) + woff;
    const uint32_t w_lo_base = smem_u32(w_lo) + woff;
    const uint32_t a_bases[2][2] = {
        { smem_u32(a0h) + aoff, smem_u32(a0l) + aoff },
        { smem_u32(a1h) + aoff, smem_u32(a1l) + aoff } };

    float bias2[4][2];
#pragma unroll
    for (int ni = 0; ni < 4; ni++) {
        bias2[ni][0] = __ldg(B + warp_n * 32 + ni * 8 + cquad);
        bias2[ni][1] = __ldg(B + warp_n * 32 + ni * 8 + cquad + 1);
    }
    float csum[8], csq[8];
#pragma unroll
    for (int j = 0; j < 8; j++) { csum[j] = 0.f; csq[j] = 0.f; }

    int p = 0;
    int tile = blockIdx.x;
    if (tile < ntiles) issue_tile(tile, a0h, a0l);

    for (; tile < ntiles; tile += gridDim.x) {
        const int row0 = tile * 128;
        int tnext = tile + gridDim.x;
        if (tnext < ntiles) {
            issue_tile(tnext, p ? a0h : a1h, p ? a0l : a1l);
            asm volatile("cp.async.wait_group 1;");
        } else {
            asm volatile("cp.async.wait_group 0;");
        }
        __syncthreads();

        const uint32_t a_hi_base = a_bases[p][0];
        const uint32_t a_lo_base = a_bases[p][1];

        float acc[2][4][4];
#pragma unroll
        for (int mi = 0; mi < 2; mi++)
#pragma unroll
            for (int ni = 0; ni < 4; ni++)
#pragma unroll
                for (int q = 0; q < 4; q++) acc[mi][ni][q] = 0.f;

#pragma unroll
        for (int k0 = 0; k0 < K; k0 += 16) {
            uint32_t ah[2][4], al[2][4];
            LDSM4(ah[0], a_hi_base + (0 * 16 * AS + k0) * 2);
            LDSM4(ah[1], a_hi_base + (1 * 16 * AS + k0) * 2);
            LDSM4(al[0], a_lo_base + (0 * 16 * AS + k0) * 2);
            LDSM4(al[1], a_lo_base + (1 * 16 * AS + k0) * 2);
            uint32_t bh0[4], bh1[4], bl0[4], bl1[4];
            LDSM4T(bh0, w_hi_base + (k0 * WS + 0) * 2);
            LDSM4T(bh1, w_hi_base + (k0 * WS + 16) * 2);
            LDSM4T(bl0, w_lo_base + (k0 * WS + 0) * 2);
            LDSM4T(bl1, w_lo_base + (k0 * WS + 16) * 2);
#pragma unroll
            for (int mi = 0; mi < 2; mi++) {
                MMA16816(acc[mi][0], ah[mi], bh0[0], bh0[1]);
                MMA16816(acc[mi][1], ah[mi], bh0[2], bh0[3]);
                MMA16816(acc[mi][2], ah[mi], bh1[0], bh1[1]);
                MMA16816(acc[mi][3], ah[mi], bh1[2], bh1[3]);
                MMA16816(acc[mi][0], ah[mi], bl0[0], bl0[1]);
                MMA16816(acc[mi][1], ah[mi], bl0[2], bl0[3]);
                MMA16816(acc[mi][2], ah[mi], bl1[0], bl1[1]);
                MMA16816(acc[mi][3], ah[mi], bl1[2], bl1[3]);
                MMA16816(acc[mi][0], al[mi], bh0[0], bh0[1]);
                MMA16816(acc[mi][1], al[mi], bh0[2], bh0[3]);
                MMA16816(acc[mi][2], al[mi], bh1[0], bh1[1]);
                MMA16816(acc[mi][3], al[mi], bh1[2], bh1[3]);
            }
        }

#pragma unroll
        for (int mi = 0; mi < 2; mi++) {
#pragma unroll
            for (int ri = 0; ri < 2; ri++) {
                int row = row0 + warp_m * 32 + mi * 16 + ri * 8 + rbase;
                if (row < N) {
                    float* yr = Y + (long long)row * 128 + warp_n * 32;
#pragma unroll
                    for (int ni = 0; ni < 4; ni++) {
                        float o0 = fmaxf(acc[mi][ni][ri * 2 + 0] + bias2[ni][0], 0.f);
                        float o1 = fmaxf(acc[mi][ni][ri * 2 + 1] + bias2[ni][1], 0.f);
                        csum[ni * 2 + 0] += o0;
                        csum[ni * 2 + 1] += o1;
                        csq[ni * 2 + 0] = fmaf(o0, o0, csq[ni * 2 + 0]);
                        csq[ni * 2 + 1] = fmaf(o1, o1, csq[ni * 2 + 1]);
                        *(float2*)(yr + ni * 8 + cquad) = make_float2(o0, o1);
                    }
                }
            }
        }
        __syncthreads();
        p ^= 1;
    }

#pragma unroll
    for (int j = 0; j < 8; j++) {
        float s = csum[j], q = csq[j];
#pragma unroll
        for (int o = 4; o <= 16; o <<= 1) {
            s += __shfl_xor_sync(0xFFFFFFFFu, s, o);
            q += __shfl_xor_sync(0xFFFFFFFFu, q, o);
        }
        if (rbase == 0) {
            int col = warp_n * 32 + (j >> 1) * 8 + cquad + (j & 1);
            atomicAdd(&gsum[col], s);
            atomicAdd(&gss[col], q);
        }
    }
}

// ---------------- fold BN1 into W2/b2 ----------------
__global__ void k_fold1(const float* __restrict__ W2, const float* __restrict__ b2,
                        const float* __restrict__ g1, const float* __restrict__ be1,
                        float invN) {
    __shared__ float a_s[128], c_s[128];
    int j = threadIdx.x;
    float mean = g_sum1[j] * invN;
    float var  = g_ss1[j] * invN - mean * mean;
    float a    = g1[j] * rsqrtf(var + BN_EPS);
    a_s[j] = a;
    c_s[j] = be1[j] - a * mean;
    __syncthreads();
    float acc = 0.f;
    for (int k = 0; k < 128; k++) {
        float w = W2[k * 128 + j];
        g_W2f[k * 128 + j] = a_s[k] * w;
        acc = fmaf(c_s[k], w, acc);
    }
    g_b2f[j] = b2[j] + acc;
}
__global__ void k_a2c2(const float* __restrict__ g2, const float* __restrict__ be2, float invN) {
    int j = threadIdx.x;
    float mean = g_sum2[j] * invN;
    float var  = g_ss2[j] * invN - mean * mean;
    float a    = g2[j] * rsqrtf(var + BN_EPS);
    g_a2[j] = a;
    g_c2[j] = be2[j] - a * mean;
}
__global__ void k_bn2(float4* __restrict__ Y, int n4) {
    int stride = gridDim.x * blockDim.x;
    for (int i = blockIdx.x * blockDim.x + threadIdx.x; i < n4; i += stride) {
        int c4 = i & 31;
        float4 v = Y[i];
        float4 a = __ldg((const float4*)g_a2 + c4);
        float4 c = __ldg((const float4*)g_c2 + c4);
        v.x = fmaf(a.x, v.x, c.x);
        v.y = fmaf(a.y, v.y, c.y);
        v.z = fmaf(a.z, v.z, c.z);
        v.w = fmaf(a.w, v.w, c.w);
        Y[i] = v;
    }
}

// ---------------- launcher ----------------
extern "C" void kernel_launch(void* const* d_in, const int* in_sizes, int n_in,
                              void* d_out, int out_size) {
    const float* x   = (const float*)d_in[0];
    const void*  eix = d_in[1];
    const float* W1  = (const float*)d_in[2];
    const float* b1  = (const float*)d_in[3];
    const float* g1  = (const float*)d_in[4];
    const float* be1 = (const float*)d_in[5];
    const float* W2  = (const float*)d_in[6];
    const float* b2  = (const float*)d_in[7];
    const float* g2  = (const float*)d_in[8];
    const float* be2 = (const float*)d_in[9];
    float* out = (float*)d_out;

    const int N = in_sizes[0] / 64;
    const int E = in_sizes[1] / 2;

    const int SMEM1 = (2 * 64 * 136 + 4 * 128 * 72) * 2;     // 108 544
    const int SMEM2 = (2 * 128 * 136 + 4 * 128 * 136) * 2;   // 208 896
    cudaFuncSetAttribute(k_gemm1, cudaFuncAttributeMaxDynamicSharedMemorySize, SMEM1);
    cudaFuncSetAttribute(k_gemm2, cudaFuncAttributeMaxDynamicSharedMemorySize, SMEM2);

    void *p_h0h, *p_h0l, *p_h1h, *p_h1l, *p_W2f, *p_b2f, *p_s1, *p_q1, *p_s2, *p_q2;
    cudaGetSymbolAddress(&p_h0h, g_h0h);
    cudaGetSymbolAddress(&p_h0l, g_h0l);
    cudaGetSymbolAddress(&p_h1h, g_h1h);
    cudaGetSymbolAddress(&p_h1l, g_h1l);
    cudaGetSymbolAddress(&p_W2f, g_W2f);
    cudaGetSymbolAddress(&p_b2f, g_b2f);
    cudaGetSymbolAddress(&p_s1, g_sum1);
    cudaGetSymbolAddress(&p_q1, g_ss1);
    cudaGetSymbolAddress(&p_s2, g_sum2);
    cudaGetSymbolAddress(&p_q2, g_ss2);

    const int GB = 148 * 8;
    const int ntiles = (N + 127) / 128;
    const int gb = ntiles < 148 ? ntiles : 148;
    const int nb_scan = (N + 511) / 512;
    const float invN = 1.0f / (float)N;

    k_zero<<<GB, 256>>>(N);
    k_detect<<<1, 256>>>((const int*)eix, E);
    k_hist<<<GB, 256>>>(eix, E);
    k_scanA<<<nb_scan, 512>>>(N);
    k_scanB<<<1, 512>>>(nb_scan);
    k_scanC<<<GB, 256>>>(N, E);
    k_permute<<<GB, 256>>>(eix, E);
    k_aggregate<<<148 * 4, 512>>>(x, N);
    k_gemm1<<<gb, 512, SMEM1>>>(
        (const __nv_bfloat16*)p_h0h, (const __nv_bfloat16*)p_h0l, W1, b1,
        (__nv_bfloat16*)p_h1h, (__nv_bfloat16*)p_h1l,
        N, ntiles, (float*)p_s1, (float*)p_q1);
    k_fold1<<<1, 128>>>(W2, b2, g1, be1, invN);
    k_gemm2<<<gb, 512, SMEM2>>>(
        (const __nv_bfloat16*)p_h1h, (const __nv_bfloat16*)p_h1l,
        (const float*)p_W2f, (const float*)p_b2f, out, N, ntiles,
        (float*)p_s2, (float*)p_q2);
    k_a2c2<<<1, 128>>>(g2, be2, invN);
    k_bn2<<<GB, 256>>>((float4*)out, N * 32);
}